// round 1
// baseline (speedup 1.0000x reference)
#include <cuda_runtime.h>

#define NN 50000
#define NE 800000
#define HHID 128
#define OOUT 32
#define BN_EPS 1e-5f

// ---------------- scratch (static device globals; no allocation) ----------------
__device__ int   g_is64;
__device__ int   g_deg[NN];
__device__ float g_dis[NN];
__device__ float g_h[NN * HHID];
__device__ float g_agg[NN * HHID];
__device__ float g_x[NN * HHID];
__device__ float g_stats[2 * HHID];   // per-channel sum, sumsq
__device__ float g_scale[HHID];
__device__ float g_shift[HHID];

// ---------------- int64-vs-int32 edge_index detection ----------------
// If the data is int64 little-endian, every odd int32 word is the high half of a
// value < 50000 -> zero. If int32, odd words are random node ids (P(all 64 == 0) ~ 0).
__global__ void k_detect(const int* __restrict__ ei32) {
    if (threadIdx.x == 0) {
        int all0 = 1;
#pragma unroll
        for (int i = 0; i < 64; i++) all0 &= (ei32[2 * i + 1] == 0);
        g_is64 = all0;
    }
}

__global__ void k_zerodeg() {
    int i = blockIdx.x * 256 + threadIdx.x;
    if (i < NN) g_deg[i] = 0;
}

__global__ void k_deg(const void* __restrict__ ei) {
    int e = blockIdx.x * 256 + threadIdx.x;
    if (e >= NE) return;
    int d = g_is64 ? (int)((const long long*)ei)[NE + e]
                   : ((const int*)ei)[NE + e];
    atomicAdd(&g_deg[d], 1);
}

__global__ void k_dis() {
    int i = blockIdx.x * 256 + threadIdx.x;
    if (i < NN) g_dis[i] = rsqrtf((float)g_deg[i] + 1.0f);
}

// ---------------- GEMM: C[N][HO] = A[N][128] @ W[128][HO] (no bias here) ----------------
// Block = 256 threads, tile 64 rows x HO cols. TM=8 rows/thread, TN=HO/32 cols/thread.
// K processed in two 64-chunks; A-tile and W-chunk in smem (exactly 48KB for HO=128).
template <int HO>
__global__ void k_gemm(const float* __restrict__ A, const float* __restrict__ W,
                       float* __restrict__ C) {
    constexpr int TN = HO / 32;
    __shared__ float As[64][64];
    __shared__ float Ws[64][HO];
    int t = threadIdx.x;
    int tx = t & 31, ty = t >> 5;
    int row0 = blockIdx.x * 64;

    float acc[8][TN];
#pragma unroll
    for (int r = 0; r < 8; r++)
#pragma unroll
        for (int j = 0; j < TN; j++) acc[r][j] = 0.f;

    for (int kk = 0; kk < 128; kk += 64) {
        // load A tile [64 x 64] (contiguous float4 stores -> conflict-free)
#pragma unroll
        for (int i = 0; i < 4; i++) {
            int idx = t + i * 256;          // 0..1023
            int r = idx >> 4;
            int c = (idx & 15) * 4;
            int row = row0 + r;
            float4 v = make_float4(0.f, 0.f, 0.f, 0.f);
            if (row < NN) v = *(const float4*)&A[row * 128 + kk + c];
            *(float4*)&As[r][c] = v;
        }
        // load W chunk [64 x HO]
#pragma unroll
        for (int i = 0; i < (64 * HO) / 1024; i++) {
            int idx = t + i * 256;
            int r = idx / (HO / 4);
            int c = (idx % (HO / 4)) * 4;
            *(float4*)&Ws[r][c] = *(const float4*)&W[(kk + r) * HO + c];
        }
        __syncthreads();

#pragma unroll
        for (int k = 0; k < 64; k++) {
            if constexpr (TN == 4) {
                float4 wv = *(const float4*)&Ws[k][tx * 4];
#pragma unroll
                for (int r = 0; r < 8; r++) {
                    float a = As[ty * 8 + r][k];
                    acc[r][0] += a * wv.x;
                    acc[r][1] += a * wv.y;
                    acc[r][2] += a * wv.z;
                    acc[r][3] += a * wv.w;
                }
            } else {
                float wv = Ws[k][tx];
#pragma unroll
                for (int r = 0; r < 8; r++) acc[r][0] += As[ty * 8 + r][k] * wv;
            }
        }
        __syncthreads();
    }

#pragma unroll
    for (int r = 0; r < 8; r++) {
        int row = row0 + ty * 8 + r;
        if (row < NN) {
            if constexpr (TN == 4) {
                float4 v = make_float4(acc[r][0], acc[r][1], acc[r][2], acc[r][3]);
                *(float4*)&C[row * HO + tx * 4] = v;
            } else {
                C[row * HO + tx] = acc[r][0];
            }
        }
    }
}

// ---------------- agg init: agg = h * dis^2 + b  (also zeroes BN stats) ----------------
template <int HO>
__global__ void k_init(const float* __restrict__ hbuf, float* __restrict__ aggbuf,
                       const float* __restrict__ b) {
    if (blockIdx.x == 0 && threadIdx.x < 2 * HHID) g_stats[threadIdx.x] = 0.f;
    int i = blockIdx.x * 256 + threadIdx.x;
    if (i >= NN * (HO / 4)) return;
    int row = i / (HO / 4);
    int c = (i % (HO / 4)) * 4;
    float inv = g_dis[row];
    inv *= inv;                      // = 1/deg
    float4 h = *(const float4*)&hbuf[row * HO + c];
    float4 bb = *(const float4*)&b[c];
    float4 o;
    o.x = fmaf(h.x, inv, bb.x);
    o.y = fmaf(h.y, inv, bb.y);
    o.z = fmaf(h.z, inv, bb.z);
    o.w = fmaf(h.w, inv, bb.w);
    *(float4*)&aggbuf[row * HO + c] = o;
}

// ---------------- edge scatter: agg[dst] += h[src] * dis[src]*dis[dst] ----------------
__device__ __forceinline__ void red_add_v4(float* p, float4 v) {
    asm volatile("red.global.add.v4.f32 [%0], {%1, %2, %3, %4};"
                 :: "l"(p), "f"(v.x), "f"(v.y), "f"(v.z), "f"(v.w)
                 : "memory");
}

__global__ void k_scatter128(const void* __restrict__ ei,
                             const float* __restrict__ hbuf,
                             float* __restrict__ aggbuf) {
    int gid = blockIdx.x * 256 + threadIdx.x;
    int e = gid >> 5;
    if (e >= NE) return;
    int lane = gid & 31;
    int s, d;
    if (g_is64) {
        const long long* p = (const long long*)ei;
        s = (int)p[e];
        d = (int)p[NE + e];
    } else {
        const int* p = (const int*)ei;
        s = p[e];
        d = p[NE + e];
    }
    float nrm = g_dis[s] * g_dis[d];
    float4 v = *(const float4*)&hbuf[s * 128 + lane * 4];
    v.x *= nrm; v.y *= nrm; v.z *= nrm; v.w *= nrm;
    red_add_v4(&aggbuf[d * 128 + lane * 4], v);
}

__global__ void k_scatter32(const void* __restrict__ ei,
                            const float* __restrict__ hbuf,
                            float* __restrict__ aggbuf) {
    int gid = blockIdx.x * 256 + threadIdx.x;
    int e = gid >> 3;
    if (e >= NE) return;
    int sub = gid & 7;
    int s, d;
    if (g_is64) {
        const long long* p = (const long long*)ei;
        s = (int)p[e];
        d = (int)p[NE + e];
    } else {
        const int* p = (const int*)ei;
        s = p[e];
        d = p[NE + e];
    }
    float nrm = g_dis[s] * g_dis[d];
    float4 v = *(const float4*)&hbuf[s * 32 + sub * 4];
    v.x *= nrm; v.y *= nrm; v.z *= nrm; v.w *= nrm;
    red_add_v4(&aggbuf[d * 32 + sub * 4], v);
}

// ---------------- BN stats: per-channel sum / sumsq over all rows ----------------
__global__ void k_bnstats(const float* __restrict__ aggbuf) {
    int t = threadIdx.x;
    int c = t & 127;
    float s = 0.f, s2 = 0.f;
    for (int row = blockIdx.x * 2 + (t >> 7); row < NN; row += gridDim.x * 2) {
        float v = aggbuf[row * 128 + c];
        s += v;
        s2 += v * v;
    }
    __shared__ float sh[256], sh2[256];
    sh[t] = s; sh2[t] = s2;
    __syncthreads();
    if (t < 128) {
        s = sh[t] + sh[t + 128];
        s2 = sh2[t] + sh2[t + 128];
        atomicAdd(&g_stats[t], s);
        atomicAdd(&g_stats[128 + t], s2);
    }
}

__global__ void k_bnfinal(const float* __restrict__ g, const float* __restrict__ be) {
    int c = threadIdx.x;   // 128 threads
    float mu = g_stats[c] * (1.0f / NN);
    float var = g_stats[128 + c] * (1.0f / NN) - mu * mu;
    float sc = g[c] * rsqrtf(var + BN_EPS);
    g_scale[c] = sc;
    g_shift[c] = be[c] - mu * sc;
}

// ---------------- BN apply + ReLU + residual ----------------
__global__ void k_apply(const float* __restrict__ aggbuf, const float* __restrict__ xin,
                        float* __restrict__ xout) {
    int i = blockIdx.x * 256 + threadIdx.x;
    if (i >= NN * 32) return;
    int row = i >> 5;
    int c = (i & 31) * 4;
    float4 a = *(const float4*)&aggbuf[row * 128 + c];
    float4 sc = *(const float4*)&g_scale[c];
    float4 sh = *(const float4*)&g_shift[c];
    float4 r = *(const float4*)&xin[row * 128 + c];
    float4 o;
    o.x = fmaxf(fmaf(a.x, sc.x, sh.x), 0.f) + r.x;
    o.y = fmaxf(fmaf(a.y, sc.y, sh.y), 0.f) + r.y;
    o.z = fmaxf(fmaf(a.z, sc.z, sh.z), 0.f) + r.z;
    o.w = fmaxf(fmaf(a.w, sc.w, sh.w), 0.f) + r.w;
    *(float4*)&xout[row * 128 + c] = o;
}

// ---------------- log_softmax over 32 classes (one warp per row) ----------------
__global__ void k_lsm(const float* __restrict__ aggbuf, float* __restrict__ out) {
    int gid = blockIdx.x * 256 + threadIdx.x;
    int row = gid >> 5;
    if (row >= NN) return;
    int lane = gid & 31;
    float v = aggbuf[row * 32 + lane];
    float m = v;
#pragma unroll
    for (int o = 16; o > 0; o >>= 1) m = fmaxf(m, __shfl_xor_sync(0xffffffffu, m, o));
    float e = __expf(v - m);
    float s = e;
#pragma unroll
    for (int o = 16; o > 0; o >>= 1) s += __shfl_xor_sync(0xffffffffu, s, o);
    out[row * 32 + lane] = v - m - logf(s);
}

// ---------------- launch ----------------
extern "C" void kernel_launch(void* const* d_in, const int* in_sizes, int n_in,
                              void* d_out, int out_size) {
    const float* x   = (const float*)d_in[0];
    const void*  ei  = d_in[1];
    const float* W0  = (const float*)d_in[2];
    const float* b0  = (const float*)d_in[3];
    const float* g0  = (const float*)d_in[4];
    const float* be0 = (const float*)d_in[5];
    const float* W1  = (const float*)d_in[6];
    const float* b1  = (const float*)d_in[7];
    const float* g1  = (const float*)d_in[8];
    const float* be1 = (const float*)d_in[9];
    const float* W2  = (const float*)d_in[10];
    const float* b2  = (const float*)d_in[11];
    float* out = (float*)d_out;

    float *p_h, *p_agg, *p_x;
    cudaGetSymbolAddress((void**)&p_h, g_h);
    cudaGetSymbolAddress((void**)&p_agg, g_agg);
    cudaGetSymbolAddress((void**)&p_x, g_x);

    k_detect<<<1, 32>>>((const int*)ei);
    k_zerodeg<<<(NN + 255) / 256, 256>>>();
    k_deg<<<(NE + 255) / 256, 256>>>(ei);
    k_dis<<<(NN + 255) / 256, 256>>>();

    const int gemmBlocks = (NN + 63) / 64;
    const int ew4   = (NN * 32 + 255) / 256;   // NN*128/4 float4 lanes
    const int ew8   = (NN * 8 + 255) / 256;    // NN*32/4
    const int sc128 = (NE * 32 + 255) / 256;   // warp per edge
    const int sc32  = (NE * 8 + 255) / 256;    // 8 lanes per edge

    // ---- layer 0 ----
    k_gemm<128><<<gemmBlocks, 256>>>(x, W0, p_h);
    k_init<128><<<ew4, 256>>>(p_h, p_agg, b0);
    k_scatter128<<<sc128, 256>>>(ei, p_h, p_agg);
    k_bnstats<<<512, 256>>>(p_agg);
    k_bnfinal<<<1, 128>>>(g0, be0);
    k_apply<<<ew4, 256>>>(p_agg, x, p_x);

    // ---- layer 1 ----
    k_gemm<128><<<gemmBlocks, 256>>>(p_x, W1, p_h);
    k_init<128><<<ew4, 256>>>(p_h, p_agg, b1);
    k_scatter128<<<sc128, 256>>>(ei, p_h, p_agg);
    k_bnstats<<<512, 256>>>(p_agg);
    k_bnfinal<<<1, 128>>>(g1, be1);
    k_apply<<<ew4, 256>>>(p_agg, p_x, p_x);

    // ---- final conv + log_softmax ----
    k_gemm<32><<<gemmBlocks, 256>>>(p_x, W2, p_h);
    k_init<32><<<ew8, 256>>>(p_h, p_agg, b2);
    k_scatter32<<<sc32, 256>>>(ei, p_h, p_agg);
    k_lsm<<<(NN * 32 + 255) / 256, 256>>>(p_agg, out);
}

// round 2
// speedup vs baseline: 1.2595x; 1.2595x over previous
#include <cuda_runtime.h>

#define NN 50000
#define NE 800000
#define NB1 49            // ceil(NN/1024)
#define BN_EPS 1e-5f

// ---------------- scratch (static device globals; no allocation) ----------------
__device__ int   g_is64;
__device__ int   g_deg[NN];
__device__ int   g_rowstart[NN];
__device__ int   g_cursor[NN];
__device__ int   g_csrc[NE];
__device__ int   g_bsum[NB1];
__device__ int   g_boff[NB1];
__device__ float g_dis[NN];
__device__ float g_h[NN * 128];
__device__ float g_agg[NN * 128];
__device__ float g_x[NN * 128];
__device__ float g_stats[256];    // [0:128) sum, [128:256) sumsq
__device__ float g_scale[128];
__device__ float g_shift[128];

// ---------------- int64-vs-int32 edge_index detection ----------------
__global__ void k_detect(const int* __restrict__ ei32) {
    if (threadIdx.x == 0) {
        int all0 = 1;
#pragma unroll
        for (int i = 0; i < 64; i++) all0 &= (ei32[2 * i + 1] == 0);
        g_is64 = all0;
    }
}

__global__ void k_zerodeg() {
    int i = blockIdx.x * 256 + threadIdx.x;
    if (i < NN) g_deg[i] = 0;
}

__global__ void k_deg(const void* __restrict__ ei) {
    int e = blockIdx.x * 256 + threadIdx.x;
    if (e >= NE) return;
    int d = g_is64 ? (int)((const long long*)ei)[NE + e]
                   : ((const int*)ei)[NE + e];
    atomicAdd(&g_deg[d], 1);
}

// ---------------- CSR build: scan over degrees ----------------
__global__ void k_scan1() {
    __shared__ int sd[1024];
    int t = threadIdx.x;
    int i = blockIdx.x * 1024 + t;
    int v = (i < NN) ? g_deg[i] : 0;
    sd[t] = v;
    __syncthreads();
#pragma unroll
    for (int off = 1; off < 1024; off <<= 1) {
        int x = (t >= off) ? sd[t - off] : 0;
        __syncthreads();
        sd[t] += x;
        __syncthreads();
    }
    if (i < NN) g_rowstart[i] = sd[t] - v;   // exclusive within block
    if (t == 1023) g_bsum[blockIdx.x] = sd[1023];
}

__global__ void k_scan2() {
    __shared__ int sd[64];
    int t = threadIdx.x;
    int v = (t < NB1) ? g_bsum[t] : 0;
    sd[t] = v;
    __syncthreads();
#pragma unroll
    for (int off = 1; off < 64; off <<= 1) {
        int x = (t >= off) ? sd[t - off] : 0;
        __syncthreads();
        sd[t] += x;
        __syncthreads();
    }
    if (t < NB1) g_boff[t] = sd[t] - v;      // exclusive block offsets
}

__global__ void k_scan3() {
    int i = blockIdx.x * 256 + threadIdx.x;
    if (i < 256) g_stats[i] = 0.f;           // zero BN stats for layer 0
    if (i >= NN) return;
    int st = g_rowstart[i] + g_boff[i >> 10];
    g_rowstart[i] = st;
    g_cursor[i] = st;
    g_dis[i] = rsqrtf((float)g_deg[i] + 1.0f);
}

__global__ void k_fill(const void* __restrict__ ei) {
    int e = blockIdx.x * 256 + threadIdx.x;
    if (e >= NE) return;
    int s, d;
    if (g_is64) {
        const long long* p = (const long long*)ei;
        s = (int)p[e]; d = (int)p[NE + e];
    } else {
        const int* p = (const int*)ei;
        s = p[e]; d = p[NE + e];
    }
    int pos = atomicAdd(&g_cursor[d], 1);
    g_csrc[pos] = s;
}

// ---------------- GEMM: C[N][HO] = A_eff[N][128] @ W[128][HO] ----------------
// MODE 0: A_eff = A (raw)
// MODE 1: A_eff = relu(A*scale+shift) + res, also stores A_eff to xout
// MODE 2: A_eff = relu(A*scale+shift) + res, no store
template <int HO, int MODE>
__global__ void k_gemm(const float* __restrict__ A, const float* __restrict__ W,
                       float* __restrict__ C, const float* __restrict__ res,
                       float* __restrict__ xout) {
    constexpr int TN = HO / 32;
    __shared__ float As[64][64];
    __shared__ float Ws[64][HO];
    int t = threadIdx.x;
    int tx = t & 31, ty = t >> 5;
    int row0 = blockIdx.x * 64;

    float acc[8][TN];
#pragma unroll
    for (int r = 0; r < 8; r++)
#pragma unroll
        for (int j = 0; j < TN; j++) acc[r][j] = 0.f;

    for (int kk = 0; kk < 128; kk += 64) {
        // load (+ optionally fuse BN/ReLU/residual into) A tile [64 x 64]
#pragma unroll
        for (int i = 0; i < 4; i++) {
            int idx = t + i * 256;
            int r = idx >> 4;
            int c = (idx & 15) * 4;
            int row = row0 + r;
            float4 v = make_float4(0.f, 0.f, 0.f, 0.f);
            if (row < NN) {
                v = *(const float4*)&A[row * 128 + kk + c];
                if constexpr (MODE >= 1) {
                    float4 sc = *(const float4*)&g_scale[kk + c];
                    float4 sh = *(const float4*)&g_shift[kk + c];
                    float4 rr = *(const float4*)&res[row * 128 + kk + c];
                    v.x = fmaxf(fmaf(v.x, sc.x, sh.x), 0.f) + rr.x;
                    v.y = fmaxf(fmaf(v.y, sc.y, sh.y), 0.f) + rr.y;
                    v.z = fmaxf(fmaf(v.z, sc.z, sh.z), 0.f) + rr.z;
                    v.w = fmaxf(fmaf(v.w, sc.w, sh.w), 0.f) + rr.w;
                    if constexpr (MODE == 1)
                        *(float4*)&xout[row * 128 + kk + c] = v;
                }
            }
            *(float4*)&As[r][c] = v;
        }
        // load W chunk [64 x HO]
#pragma unroll
        for (int i = 0; i < (64 * HO) / 1024; i++) {
            int idx = t + i * 256;
            int r = idx / (HO / 4);
            int c = (idx % (HO / 4)) * 4;
            *(float4*)&Ws[r][c] = *(const float4*)&W[(kk + r) * HO + c];
        }
        __syncthreads();

#pragma unroll
        for (int k = 0; k < 64; k++) {
            if constexpr (TN == 4) {
                float4 wv = *(const float4*)&Ws[k][tx * 4];
#pragma unroll
                for (int r = 0; r < 8; r++) {
                    float a = As[ty * 8 + r][k];
                    acc[r][0] += a * wv.x;
                    acc[r][1] += a * wv.y;
                    acc[r][2] += a * wv.z;
                    acc[r][3] += a * wv.w;
                }
            } else {
                float wv = Ws[k][tx];
#pragma unroll
                for (int r = 0; r < 8; r++) acc[r][0] += As[ty * 8 + r][k] * wv;
            }
        }
        __syncthreads();
    }

#pragma unroll
    for (int r = 0; r < 8; r++) {
        int row = row0 + ty * 8 + r;
        if (row < NN) {
            if constexpr (TN == 4) {
                float4 v = make_float4(acc[r][0], acc[r][1], acc[r][2], acc[r][3]);
                *(float4*)&C[row * HO + tx * 4] = v;
            } else {
                C[row * HO + tx] = acc[r][0];
            }
        }
    }
}

// ---------------- CSR gather (128ch): agg[d] = sum_in h[s]*dis[s]*dis[d] + h[d]/deg + b
// Fuses BN-stat accumulation (sum, sumsq per channel).
__global__ void k_gather128(const float* __restrict__ h, float* __restrict__ agg,
                            const float* __restrict__ b) {
    __shared__ float ssum[128], ssum2[128];
    int t = threadIdx.x;
    if (t < 128) { ssum[t] = 0.f; ssum2[t] = 0.f; }
    int w = t >> 5, lane = t & 31;
    int d = blockIdx.x * 8 + w;
    float4 acc = make_float4(0.f, 0.f, 0.f, 0.f);
    bool valid = d < NN;
    if (valid) {
        float disd = g_dis[d];
        float inv = disd * disd;
        float4 hv = *(const float4*)&h[d * 128 + lane * 4];
        float4 bv = *(const float4*)&b[lane * 4];
        acc.x = fmaf(hv.x, inv, bv.x);
        acc.y = fmaf(hv.y, inv, bv.y);
        acc.z = fmaf(hv.z, inv, bv.z);
        acc.w = fmaf(hv.w, inv, bv.w);
        int j = g_rowstart[d];
        int end = j + g_deg[d];
        for (; j + 4 <= end; j += 4) {
            int s0 = g_csrc[j + 0], s1 = g_csrc[j + 1];
            int s2 = g_csrc[j + 2], s3 = g_csrc[j + 3];
            float w0 = g_dis[s0] * disd, w1 = g_dis[s1] * disd;
            float w2 = g_dis[s2] * disd, w3 = g_dis[s3] * disd;
            float4 v0 = *(const float4*)&h[s0 * 128 + lane * 4];
            float4 v1 = *(const float4*)&h[s1 * 128 + lane * 4];
            float4 v2 = *(const float4*)&h[s2 * 128 + lane * 4];
            float4 v3 = *(const float4*)&h[s3 * 128 + lane * 4];
            acc.x = fmaf(v0.x, w0, acc.x); acc.y = fmaf(v0.y, w0, acc.y);
            acc.z = fmaf(v0.z, w0, acc.z); acc.w = fmaf(v0.w, w0, acc.w);
            acc.x = fmaf(v1.x, w1, acc.x); acc.y = fmaf(v1.y, w1, acc.y);
            acc.z = fmaf(v1.z, w1, acc.z); acc.w = fmaf(v1.w, w1, acc.w);
            acc.x = fmaf(v2.x, w2, acc.x); acc.y = fmaf(v2.y, w2, acc.y);
            acc.z = fmaf(v2.z, w2, acc.z); acc.w = fmaf(v2.w, w2, acc.w);
            acc.x = fmaf(v3.x, w3, acc.x); acc.y = fmaf(v3.y, w3, acc.y);
            acc.z = fmaf(v3.z, w3, acc.z); acc.w = fmaf(v3.w, w3, acc.w);
        }
        for (; j < end; j++) {
            int s = g_csrc[j];
            float ww = g_dis[s] * disd;
            float4 v = *(const float4*)&h[s * 128 + lane * 4];
            acc.x = fmaf(v.x, ww, acc.x); acc.y = fmaf(v.y, ww, acc.y);
            acc.z = fmaf(v.z, ww, acc.z); acc.w = fmaf(v.w, ww, acc.w);
        }
        *(float4*)&agg[d * 128 + lane * 4] = acc;
    }
    // BN stats: block-level smem reduction, then one global RED per channel/block
    __syncthreads();
    if (valid) {
        int c = lane * 4;
        atomicAdd(&ssum[c + 0], acc.x);  atomicAdd(&ssum2[c + 0], acc.x * acc.x);
        atomicAdd(&ssum[c + 1], acc.y);  atomicAdd(&ssum2[c + 1], acc.y * acc.y);
        atomicAdd(&ssum[c + 2], acc.z);  atomicAdd(&ssum2[c + 2], acc.z * acc.z);
        atomicAdd(&ssum[c + 3], acc.w);  atomicAdd(&ssum2[c + 3], acc.w * acc.w);
    }
    __syncthreads();
    if (t < 128) {
        atomicAdd(&g_stats[t], ssum[t]);
        atomicAdd(&g_stats[128 + t], ssum2[t]);
    }
}

__global__ void k_bnfinal(const float* __restrict__ g, const float* __restrict__ be) {
    int c = threadIdx.x;   // 128 threads
    float mu = g_stats[c] * (1.0f / NN);
    float var = g_stats[128 + c] * (1.0f / NN) - mu * mu;
    float sc = g[c] * rsqrtf(var + BN_EPS);
    g_scale[c] = sc;
    g_shift[c] = be[c] - mu * sc;
    g_stats[c] = 0.f;              // reset for next layer
    g_stats[128 + c] = 0.f;
}

// ---------------- final gather (32ch) fused with log_softmax ----------------
__global__ void k_gather32_lsm(const float* __restrict__ h, float* __restrict__ out,
                               const float* __restrict__ b) {
    int t = threadIdx.x;
    int w = t >> 5, lane = t & 31;
    int d = blockIdx.x * 8 + w;
    if (d >= NN) return;
    float disd = g_dis[d];
    float inv = disd * disd;
    float acc = fmaf(h[d * 32 + lane], inv, b[lane]);
    int j = g_rowstart[d];
    int end = j + g_deg[d];
    for (; j + 4 <= end; j += 4) {
        int s0 = g_csrc[j + 0], s1 = g_csrc[j + 1];
        int s2 = g_csrc[j + 2], s3 = g_csrc[j + 3];
        float w0 = g_dis[s0] * disd, w1 = g_dis[s1] * disd;
        float w2 = g_dis[s2] * disd, w3 = g_dis[s3] * disd;
        float v0 = h[s0 * 32 + lane], v1 = h[s1 * 32 + lane];
        float v2 = h[s2 * 32 + lane], v3 = h[s3 * 32 + lane];
        acc = fmaf(v0, w0, acc);
        acc = fmaf(v1, w1, acc);
        acc = fmaf(v2, w2, acc);
        acc = fmaf(v3, w3, acc);
    }
    for (; j < end; j++) {
        int s = g_csrc[j];
        acc = fmaf(h[s * 32 + lane], g_dis[s] * disd, acc);
    }
    // log_softmax over the 32 lanes
    float m = acc;
#pragma unroll
    for (int o = 16; o > 0; o >>= 1) m = fmaxf(m, __shfl_xor_sync(0xffffffffu, m, o));
    float e = __expf(acc - m);
    float s = e;
#pragma unroll
    for (int o = 16; o > 0; o >>= 1) s += __shfl_xor_sync(0xffffffffu, s, o);
    out[d * 32 + lane] = acc - m - logf(s);
}

// ---------------- launch ----------------
extern "C" void kernel_launch(void* const* d_in, const int* in_sizes, int n_in,
                              void* d_out, int out_size) {
    const float* x   = (const float*)d_in[0];
    const void*  ei  = d_in[1];
    const float* W0  = (const float*)d_in[2];
    const float* b0  = (const float*)d_in[3];
    const float* g0  = (const float*)d_in[4];
    const float* be0 = (const float*)d_in[5];
    const float* W1  = (const float*)d_in[6];
    const float* b1  = (const float*)d_in[7];
    const float* g1  = (const float*)d_in[8];
    const float* be1 = (const float*)d_in[9];
    const float* W2  = (const float*)d_in[10];
    const float* b2  = (const float*)d_in[11];
    float* out = (float*)d_out;

    float *p_h, *p_agg, *p_x;
    cudaGetSymbolAddress((void**)&p_h, g_h);
    cudaGetSymbolAddress((void**)&p_agg, g_agg);
    cudaGetSymbolAddress((void**)&p_x, g_x);

    const int nodeBlocks = (NN + 255) / 256;      // 196
    const int edgeBlocks = (NE + 255) / 256;      // 3125
    const int gemmBlocks = (NN + 63) / 64;        // 782
    const int gatherBlocks = (NN + 7) / 8;        // 6250

    // graph preprocessing: degrees -> CSR
    k_detect<<<1, 32>>>((const int*)ei);
    k_zerodeg<<<nodeBlocks, 256>>>();
    k_deg<<<edgeBlocks, 256>>>(ei);
    k_scan1<<<NB1, 1024>>>();
    k_scan2<<<1, 64>>>();
    k_scan3<<<nodeBlocks, 256>>>();
    k_fill<<<edgeBlocks, 256>>>(ei);

    // ---- layer 0 ----
    k_gemm<128, 0><<<gemmBlocks, 256>>>(x, W0, p_h, nullptr, nullptr);
    k_gather128<<<gatherBlocks, 256>>>(p_h, p_agg, b0);
    k_bnfinal<<<1, 128>>>(g0, be0);

    // ---- layer 1 (A = relu(bn(agg0)) + x, store x1) ----
    k_gemm<128, 1><<<gemmBlocks, 256>>>(p_agg, W1, p_h, x, p_x);
    k_gather128<<<gatherBlocks, 256>>>(p_h, p_agg, b1);
    k_bnfinal<<<1, 128>>>(g1, be1);

    // ---- final conv (A = relu(bn(agg1)) + x1) + fused log_softmax ----
    k_gemm<32, 2><<<gemmBlocks, 256>>>(p_agg, W2, p_h, p_x, nullptr);
    k_gather32_lsm<<<gatherBlocks, 256>>>(p_h, out, b2);
}

// round 4
// speedup vs baseline: 1.3266x; 1.0533x over previous
#include <cuda_runtime.h>
#include <cstdint>

#define NN 50000
#define NE 800000
#define NB1 49            // ceil(NN/1024)
#define BN_EPS 1e-5f

// ---------------- scratch (static device globals; no allocation) ----------------
__device__ int   g_is64;
__device__ int   g_deg[NN];
__device__ int   g_rowstart[NN];
__device__ int   g_cursor[NN];
__device__ int   g_csrc[NE];
__device__ int   g_bsum[NB1];
__device__ int   g_boff[NB1];
__device__ float g_dis[NN];
__device__ float g_h[NN * 128];
__device__ float g_agg[NN * 128];
__device__ float g_x[NN * 128];
__device__ float g_stats[256];    // [0:128) sum, [128:256) sumsq
__device__ float g_scale[128];
__device__ float g_shift[128];

// ---------------- helpers ----------------
__device__ __forceinline__ uint32_t tf32_hi(float x) {
    uint32_t u;
    asm("cvt.rna.tf32.f32 %0, %1;" : "=r"(u) : "f"(x));
    return u;
}
__device__ __forceinline__ void split_tf32(float v, uint32_t& hi, uint32_t& lo) {
    hi = tf32_hi(v);
    lo = tf32_hi(v - __uint_as_float(hi));
}
__device__ __forceinline__ void mma8(float* d, const uint32_t* a, const uint32_t* b) {
    asm volatile(
        "mma.sync.aligned.m16n8k8.row.col.f32.tf32.tf32.f32 "
        "{%0,%1,%2,%3}, {%4,%5,%6,%7}, {%8,%9}, {%0,%1,%2,%3};"
        : "+f"(d[0]), "+f"(d[1]), "+f"(d[2]), "+f"(d[3])
        : "r"(a[0]), "r"(a[1]), "r"(a[2]), "r"(a[3]), "r"(b[0]), "r"(b[1]));
}

// ---------------- int64-vs-int32 edge_index detection ----------------
__global__ void k_detect(const int* __restrict__ ei32) {
    if (threadIdx.x == 0) {
        int all0 = 1;
#pragma unroll
        for (int i = 0; i < 64; i++) all0 &= (ei32[2 * i + 1] == 0);
        g_is64 = all0;
    }
}

__global__ void k_zerodeg() {
    int i = blockIdx.x * 256 + threadIdx.x;
    if (i < NN) g_deg[i] = 0;
}

__global__ void k_deg(const void* __restrict__ ei) {
    int e = blockIdx.x * 256 + threadIdx.x;
    if (e >= NE) return;
    int d = g_is64 ? (int)((const long long*)ei)[NE + e]
                   : ((const int*)ei)[NE + e];
    atomicAdd(&g_deg[d], 1);
}

// ---------------- CSR build ----------------
__global__ void k_scan1() {
    __shared__ int sd[1024];
    int t = threadIdx.x;
    int i = blockIdx.x * 1024 + t;
    int v = (i < NN) ? g_deg[i] : 0;
    sd[t] = v;
    __syncthreads();
#pragma unroll
    for (int off = 1; off < 1024; off <<= 1) {
        int x = (t >= off) ? sd[t - off] : 0;
        __syncthreads();
        sd[t] += x;
        __syncthreads();
    }
    if (i < NN) g_rowstart[i] = sd[t] - v;
    if (t == 1023) g_bsum[blockIdx.x] = sd[1023];
}

__global__ void k_scan2() {
    __shared__ int sd[64];
    int t = threadIdx.x;
    int v = (t < NB1) ? g_bsum[t] : 0;
    sd[t] = v;
    __syncthreads();
#pragma unroll
    for (int off = 1; off < 64; off <<= 1) {
        int x = (t >= off) ? sd[t - off] : 0;
        __syncthreads();
        sd[t] += x;
        __syncthreads();
    }
    if (t < NB1) g_boff[t] = sd[t] - v;
}

__global__ void k_scan3() {
    int i = blockIdx.x * 256 + threadIdx.x;
    if (i < 256) g_stats[i] = 0.f;
    if (i >= NN) return;
    int st = g_rowstart[i] + g_boff[i >> 10];
    g_rowstart[i] = st;
    g_cursor[i] = st;
    g_dis[i] = rsqrtf((float)g_deg[i] + 1.0f);
}

__global__ void k_fill(const void* __restrict__ ei) {
    int e = blockIdx.x * 256 + threadIdx.x;
    if (e >= NE) return;
    int s, d;
    if (g_is64) {
        const long long* p = (const long long*)ei;
        s = (int)p[e]; d = (int)p[NE + e];
    } else {
        const int* p = (const int*)ei;
        s = p[e]; d = p[NE + e];
    }
    int pos = atomicAdd(&g_cursor[d], 1);
    g_csrc[pos] = s;
}

// ---------------- 3xTF32 warp-MMA GEMM: C[N][NOUT] = A_eff[N][128] @ W[128][NOUT]
// MODE 0: A_eff = A; MODE 1: A_eff = relu(A*scale+shift)+res, store xout;
// MODE 2: same as 1 without store.
// Block: 256 thr, tile M=64 x NOUT, K=128 fully smem-resident.
// Warp grid: warp_m = wid&1 (32 rows each), warp_n = wid>>1 (NOUT/4 cols each).
template <int NOUT, int MODE>
__global__ void __launch_bounds__(256)
k_mgemm(const float* __restrict__ A, const float* __restrict__ W,
        float* __restrict__ C, const float* __restrict__ res,
        float* __restrict__ xout) {
    constexpr int WN = NOUT / 4;     // warp n-tile
    constexpr int NA = WN / 8;       // n-atoms per warp (4 for 128, 1 for 32)
    constexpr int ASTR = 132;        // A smem stride (floats), conflict-free frag loads
    constexpr int WSTR = NOUT + 8;   // W smem stride (floats), conflict-free frag loads
    extern __shared__ float sm[];
    float* As = sm;                  // [64][ASTR]
    float* Ws = sm + 64 * ASTR;      // [128][WSTR]

    const int t = threadIdx.x;
    const int lane = t & 31, wid = t >> 5;
    const int row0 = blockIdx.x * 64;

    // ---- fill A tile [64 x 128] with fused pre-op ----
#pragma unroll
    for (int i = 0; i < 8; i++) {
        int idx = t + i * 256;           // 0..2047
        int r = idx >> 5;
        int c = (idx & 31) * 4;
        int row = row0 + r;
        float4 v = make_float4(0.f, 0.f, 0.f, 0.f);
        if (row < NN) {
            v = *(const float4*)&A[row * 128 + c];
            if constexpr (MODE >= 1) {
                float4 sc = *(const float4*)&g_scale[c];
                float4 sh = *(const float4*)&g_shift[c];
                float4 rr = *(const float4*)&res[row * 128 + c];
                v.x = fmaxf(fmaf(v.x, sc.x, sh.x), 0.f) + rr.x;
                v.y = fmaxf(fmaf(v.y, sc.y, sh.y), 0.f) + rr.y;
                v.z = fmaxf(fmaf(v.z, sc.z, sh.z), 0.f) + rr.z;
                v.w = fmaxf(fmaf(v.w, sc.w, sh.w), 0.f) + rr.w;
                if constexpr (MODE == 1)
                    *(float4*)&xout[row * 128 + c] = v;
            }
        }
        *(float4*)&As[r * ASTR + c] = v;
    }
    // ---- fill W [128 x NOUT] ----
#pragma unroll
    for (int i = 0; i < NOUT / 8; i++) {
        int idx = t + i * 256;
        int k = idx / (NOUT / 4);
        int n = (idx % (NOUT / 4)) * 4;
        float4 v = *(const float4*)&W[k * NOUT + n];
        *(float4*)&Ws[k * WSTR + n] = v;
    }
    __syncthreads();

    float acc[2][NA][4];
#pragma unroll
    for (int ma = 0; ma < 2; ma++)
#pragma unroll
        for (int na = 0; na < NA; na++)
#pragma unroll
            for (int j = 0; j < 4; j++) acc[ma][na][j] = 0.f;

    const int fr = lane >> 2;        // 0..7
    const int fc = lane & 3;         // 0..3
    const int mrow = (wid & 1) * 32;
    const int ncol = (wid >> 1) * WN;

#pragma unroll
    for (int ks = 0; ks < 16; ks++) {
        const int k0 = ks * 8;
        uint32_t ah[2][4], al[2][4];
#pragma unroll
        for (int ma = 0; ma < 2; ma++) {
            int rb = mrow + ma * 16 + fr;
            split_tf32(As[rb * ASTR + k0 + fc],            ah[ma][0], al[ma][0]);
            split_tf32(As[(rb + 8) * ASTR + k0 + fc],      ah[ma][1], al[ma][1]);
            split_tf32(As[rb * ASTR + k0 + fc + 4],        ah[ma][2], al[ma][2]);
            split_tf32(As[(rb + 8) * ASTR + k0 + fc + 4],  ah[ma][3], al[ma][3]);
        }
        uint32_t bh[NA][2], bl[NA][2];
#pragma unroll
        for (int na = 0; na < NA; na++) {
            int cb = ncol + na * 8 + fr;
            split_tf32(Ws[(k0 + fc) * WSTR + cb],       bh[na][0], bl[na][0]);
            split_tf32(Ws[(k0 + fc + 4) * WSTR + cb],   bh[na][1], bl[na][1]);
        }
#pragma unroll
        for (int ma = 0; ma < 2; ma++)
#pragma unroll
            for (int na = 0; na < NA; na++) {
                mma8(acc[ma][na], ah[ma], bh[na]);
                mma8(acc[ma][na], ah[ma], bl[na]);
                mma8(acc[ma][na], al[ma], bh[na]);
            }
    }

    // ---- epilogue: direct stores (float2 per atom-half) ----
#pragma unroll
    for (int ma = 0; ma < 2; ma++) {
        int r0 = row0 + mrow + ma * 16 + fr;
#pragma unroll
        for (int na = 0; na < NA; na++) {
            int cc = ncol + na * 8 + fc * 2;
            if (r0 < NN)
                *(float2*)&C[r0 * NOUT + cc] = make_float2(acc[ma][na][0], acc[ma][na][1]);
            if (r0 + 8 < NN)
                *(float2*)&C[(r0 + 8) * NOUT + cc] = make_float2(acc[ma][na][2], acc[ma][na][3]);
        }
    }
}

// ---------------- CSR gather (128ch) + fused BN stats ----------------
__global__ void k_gather128(const float* __restrict__ h, float* __restrict__ agg,
                            const float* __restrict__ b) {
    __shared__ float ssum[128], ssum2[128];
    int t = threadIdx.x;
    if (t < 128) { ssum[t] = 0.f; ssum2[t] = 0.f; }
    int w = t >> 5, lane = t & 31;
    int d = blockIdx.x * 8 + w;
    float4 acc = make_float4(0.f, 0.f, 0.f, 0.f);
    bool valid = d < NN;
    if (valid) {
        float disd = g_dis[d];
        float inv = disd * disd;
        float4 hv = *(const float4*)&h[d * 128 + lane * 4];
        float4 bv = *(const float4*)&b[lane * 4];
        acc.x = fmaf(hv.x, inv, bv.x);
        acc.y = fmaf(hv.y, inv, bv.y);
        acc.z = fmaf(hv.z, inv, bv.z);
        acc.w = fmaf(hv.w, inv, bv.w);
        int j = g_rowstart[d];
        int end = j + g_deg[d];
        for (; j + 4 <= end; j += 4) {
            int s0 = g_csrc[j + 0], s1 = g_csrc[j + 1];
            int s2 = g_csrc[j + 2], s3 = g_csrc[j + 3];
            float w0 = g_dis[s0] * disd, w1 = g_dis[s1] * disd;
            float w2 = g_dis[s2] * disd, w3 = g_dis[s3] * disd;
            float4 v0 = *(const float4*)&h[s0 * 128 + lane * 4];
            float4 v1 = *(const float4*)&h[s1 * 128 + lane * 4];
            float4 v2 = *(const float4*)&h[s2 * 128 + lane * 4];
            float4 v3 = *(const float4*)&h[s3 * 128 + lane * 4];
            acc.x = fmaf(v0.x, w0, acc.x); acc.y = fmaf(v0.y, w0, acc.y);
            acc.z = fmaf(v0.z, w0, acc.z); acc.w = fmaf(v0.w, w0, acc.w);
            acc.x = fmaf(v1.x, w1, acc.x); acc.y = fmaf(v1.y, w1, acc.y);
            acc.z = fmaf(v1.z, w1, acc.z); acc.w = fmaf(v1.w, w1, acc.w);
            acc.x = fmaf(v2.x, w2, acc.x); acc.y = fmaf(v2.y, w2, acc.y);
            acc.z = fmaf(v2.z, w2, acc.z); acc.w = fmaf(v2.w, w2, acc.w);
            acc.x = fmaf(v3.x, w3, acc.x); acc.y = fmaf(v3.y, w3, acc.y);
            acc.z = fmaf(v3.z, w3, acc.z); acc.w = fmaf(v3.w, w3, acc.w);
        }
        for (; j < end; j++) {
            int s = g_csrc[j];
            float ww = g_dis[s] * disd;
            float4 v = *(const float4*)&h[s * 128 + lane * 4];
            acc.x = fmaf(v.x, ww, acc.x); acc.y = fmaf(v.y, ww, acc.y);
            acc.z = fmaf(v.z, ww, acc.z); acc.w = fmaf(v.w, ww, acc.w);
        }
        *(float4*)&agg[d * 128 + lane * 4] = acc;
    }
    __syncthreads();
    if (valid) {
        int c = lane * 4;
        atomicAdd(&ssum[c + 0], acc.x);  atomicAdd(&ssum2[c + 0], acc.x * acc.x);
        atomicAdd(&ssum[c + 1], acc.y);  atomicAdd(&ssum2[c + 1], acc.y * acc.y);
        atomicAdd(&ssum[c + 2], acc.z);  atomicAdd(&ssum2[c + 2], acc.z * acc.z);
        atomicAdd(&ssum[c + 3], acc.w);  atomicAdd(&ssum2[c + 3], acc.w * acc.w);
    }
    __syncthreads();
    if (t < 128) {
        atomicAdd(&g_stats[t], ssum[t]);
        atomicAdd(&g_stats[128 + t], ssum2[t]);
    }
}

__global__ void k_bnfinal(const float* __restrict__ g, const float* __restrict__ be) {
    int c = threadIdx.x;
    float mu = g_stats[c] * (1.0f / NN);
    float var = g_stats[128 + c] * (1.0f / NN) - mu * mu;
    float sc = g[c] * rsqrtf(var + BN_EPS);
    g_scale[c] = sc;
    g_shift[c] = be[c] - mu * sc;
    g_stats[c] = 0.f;
    g_stats[128 + c] = 0.f;
}

// ---------------- final gather (32ch) fused with log_softmax ----------------
__global__ void k_gather32_lsm(const float* __restrict__ h, float* __restrict__ out,
                               const float* __restrict__ b) {
    int t = threadIdx.x;
    int w = t >> 5, lane = t & 31;
    int d = blockIdx.x * 8 + w;
    if (d >= NN) return;
    float disd = g_dis[d];
    float inv = disd * disd;
    float acc = fmaf(h[d * 32 + lane], inv, b[lane]);
    int j = g_rowstart[d];
    int end = j + g_deg[d];
    for (; j + 4 <= end; j += 4) {
        int s0 = g_csrc[j + 0], s1 = g_csrc[j + 1];
        int s2 = g_csrc[j + 2], s3 = g_csrc[j + 3];
        float w0 = g_dis[s0] * disd, w1 = g_dis[s1] * disd;
        float w2 = g_dis[s2] * disd, w3 = g_dis[s3] * disd;
        float v0 = h[s0 * 32 + lane], v1 = h[s1 * 32 + lane];
        float v2 = h[s2 * 32 + lane], v3 = h[s3 * 32 + lane];
        acc = fmaf(v0, w0, acc);
        acc = fmaf(v1, w1, acc);
        acc = fmaf(v2, w2, acc);
        acc = fmaf(v3, w3, acc);
    }
    for (; j < end; j++) {
        int s = g_csrc[j];
        acc = fmaf(h[s * 32 + lane], g_dis[s] * disd, acc);
    }
    float m = acc;
#pragma unroll
    for (int o = 16; o > 0; o >>= 1) m = fmaxf(m, __shfl_xor_sync(0xffffffffu, m, o));
    float e = __expf(acc - m);
    float s = e;
#pragma unroll
    for (int o = 16; o > 0; o >>= 1) s += __shfl_xor_sync(0xffffffffu, s, o);
    out[d * 32 + lane] = acc - m - logf(s);
}

// ---------------- launch ----------------
extern "C" void kernel_launch(void* const* d_in, const int* in_sizes, int n_in,
                              void* d_out, int out_size) {
    const float* x   = (const float*)d_in[0];
    const void*  ei  = d_in[1];
    const float* W0  = (const float*)d_in[2];
    const float* b0  = (const float*)d_in[3];
    const float* g0  = (const float*)d_in[4];
    const float* be0 = (const float*)d_in[5];
    const float* W1  = (const float*)d_in[6];
    const float* b1  = (const float*)d_in[7];
    const float* g1  = (const float*)d_in[8];
    const float* be1 = (const float*)d_in[9];
    const float* W2  = (const float*)d_in[10];
    const float* b2  = (const float*)d_in[11];
    float* out = (float*)d_out;

    float *p_h, *p_agg, *p_x;
    cudaGetSymbolAddress((void**)&p_h, g_h);
    cudaGetSymbolAddress((void**)&p_agg, g_agg);
    cudaGetSymbolAddress((void**)&p_x, g_x);

    const int nodeBlocks = (NN + 255) / 256;
    const int edgeBlocks = (NE + 255) / 256;
    const int gatherBlocks = (NN + 7) / 8;
    const int mgemmBlocks = (NN + 63) / 64;       // 782

    const int SM128 = (64 * 132 + 128 * 136) * 4; // 103424
    const int SM32  = (64 * 132 + 128 * 40) * 4;  // 54272
    cudaFuncSetAttribute(k_mgemm<128, 0>, cudaFuncAttributeMaxDynamicSharedMemorySize, SM128);
    cudaFuncSetAttribute(k_mgemm<128, 1>, cudaFuncAttributeMaxDynamicSharedMemorySize, SM128);
    cudaFuncSetAttribute(k_mgemm<32, 2>,  cudaFuncAttributeMaxDynamicSharedMemorySize, SM32);

    // graph preprocessing: degrees -> CSR
    k_detect<<<1, 32>>>((const int*)ei);
    k_zerodeg<<<nodeBlocks, 256>>>();
    k_deg<<<edgeBlocks, 256>>>(ei);
    k_scan1<<<NB1, 1024>>>();
    k_scan2<<<1, 64>>>();
    k_scan3<<<nodeBlocks, 256>>>();
    k_fill<<<edgeBlocks, 256>>>(ei);

    // ---- layer 0 ----
    k_mgemm<128, 0><<<mgemmBlocks, 256, SM128>>>(x, W0, p_h, nullptr, nullptr);
    k_gather128<<<gatherBlocks, 256>>>(p_h, p_agg, b0);
    k_bnfinal<<<1, 128>>>(g0, be0);

    // ---- layer 1 ----
    k_mgemm<128, 1><<<mgemmBlocks, 256, SM128>>>(p_agg, W1, p_h, x, p_x);
    k_gather128<<<gatherBlocks, 256>>>(p_h, p_agg, b1);
    k_bnfinal<<<1, 128>>>(g1, be1);

    // ---- final conv + fused log_softmax ----
    k_mgemm<32, 2><<<mgemmBlocks, 256, SM32>>>(p_agg, W2, p_h, p_x, nullptr);
    k_gather32_lsm<<<gatherBlocks, 256>>>(p_h, out, b2);
}

// round 5
// speedup vs baseline: 1.3816x; 1.0414x over previous
#include <cuda_runtime.h>
#include <cstdint>

#define NN 50000
#define NE 800000
#define NB1 49            // ceil(NN/1024)
#define BN_EPS 1e-5f
#define CSRC_CAP (NE + 4 * NN)   // padded CSR capacity

// ---------------- scratch (static device globals; no allocation) ----------------
__device__ int   g_is64;
__device__ int   g_deg[NN];
__device__ int   g_rowstart[NN + 1];
__device__ int   g_cursor[NN];
__device__ int4  g_csrc4[CSRC_CAP / 4];
__device__ int   g_bsum[NB1];
__device__ int   g_boff[NB1];
__device__ float g_dis[NN];
__device__ float g_h[(NN + 1) * 128];     // +1: zero dummy row for padded edges
__device__ float g_agg[NN * 128];
__device__ float g_x[NN * 128];
__device__ float g_stats[512];            // two buffers of 256 (sum|sumsq)

// ---------------- helpers ----------------
__device__ __forceinline__ uint32_t tf32_hi(float x) {
    uint32_t u;
    asm("cvt.rna.tf32.f32 %0, %1;" : "=r"(u) : "f"(x));
    return u;
}
__device__ __forceinline__ void split_tf32(float v, uint32_t& hi, uint32_t& lo) {
    hi = tf32_hi(v);
    lo = tf32_hi(v - __uint_as_float(hi));
}
__device__ __forceinline__ void mma8(float* d, const uint32_t* a, const uint32_t* b) {
    asm volatile(
        "mma.sync.aligned.m16n8k8.row.col.f32.tf32.tf32.f32 "
        "{%0,%1,%2,%3}, {%4,%5,%6,%7}, {%8,%9}, {%0,%1,%2,%3};"
        : "+f"(d[0]), "+f"(d[1]), "+f"(d[2]), "+f"(d[3])
        : "r"(a[0]), "r"(a[1]), "r"(a[2]), "r"(a[3]), "r"(b[0]), "r"(b[1]));
}

// ---------------- init: zero degrees + int64/int32 detect ----------------
__global__ void k_init0(const int* __restrict__ ei32) {
    int i = blockIdx.x * 256 + threadIdx.x;
    if (i < NN) g_deg[i] = 0;
    if (blockIdx.x == 0 && threadIdx.x == 0) {
        int all0 = 1;
#pragma unroll
        for (int j = 0; j < 64; j++) all0 &= (ei32[2 * j + 1] == 0);
        g_is64 = all0;
    }
}

__global__ void k_deg(const void* __restrict__ ei) {
    int e = blockIdx.x * 256 + threadIdx.x;
    if (e >= NE) return;
    int d = g_is64 ? (int)((const long long*)ei)[NE + e]
                   : ((const int*)ei)[NE + e];
    atomicAdd(&g_deg[d], 1);
}

// ---------------- CSR build (padded degrees, multiple of 4) ----------------
__global__ void k_scan1() {
    __shared__ int sd[1024];
    int t = threadIdx.x;
    int i = blockIdx.x * 1024 + t;
    int v = (i < NN) ? ((g_deg[i] + 3) & ~3) : 0;
    sd[t] = v;
    __syncthreads();
#pragma unroll
    for (int off = 1; off < 1024; off <<= 1) {
        int x = (t >= off) ? sd[t - off] : 0;
        __syncthreads();
        sd[t] += x;
        __syncthreads();
    }
    if (i < NN) g_rowstart[i] = sd[t] - v;
    if (t == 1023) g_bsum[blockIdx.x] = sd[1023];
}

__global__ void k_scan2() {
    __shared__ int sd[64];
    int t = threadIdx.x;
    int v = (t < NB1) ? g_bsum[t] : 0;
    sd[t] = v;
    __syncthreads();
#pragma unroll
    for (int off = 1; off < 64; off <<= 1) {
        int x = (t >= off) ? sd[t - off] : 0;
        __syncthreads();
        sd[t] += x;
        __syncthreads();
    }
    if (t < NB1) g_boff[t] = sd[t] - v;
    if (t == NB1 - 1) g_rowstart[NN] = sd[t];   // total (sentinel)
}

__global__ void k_scan3() {
    int i = blockIdx.x * 256 + threadIdx.x;
    if (i < 512) g_stats[i] = 0.f;              // zero both BN stat buffers
    if (i >= NN) return;
    int st = g_rowstart[i] + g_boff[i >> 10];
    g_rowstart[i] = st;
    g_cursor[i] = st;
    g_dis[i] = rsqrtf((float)g_deg[i] + 1.0f);
}

__global__ void k_fill(const void* __restrict__ ei) {
    int e = blockIdx.x * 256 + threadIdx.x;
    if (e >= NE) return;
    int s, d;
    if (g_is64) {
        const long long* p = (const long long*)ei;
        s = (int)p[e]; d = (int)p[NE + e];
    } else {
        const int* p = (const int*)ei;
        s = p[e]; d = p[NE + e];
    }
    int pos = atomicAdd(&g_cursor[d], 1);
    ((int*)g_csrc4)[pos] = s;
}

__global__ void k_pad() {
    int i = blockIdx.x * 256 + threadIdx.x;
    if (i >= NN) return;
    int p = g_cursor[i];
    int e = g_rowstart[i + 1];
    int* cs = (int*)g_csrc4;
    for (; p < e; p++) cs[p] = NN;              // dummy -> zero row
}

// ---------------- 3xTF32 warp-MMA GEMM ----------------
// C[N][NOUT] = dis[row] * (A_eff[N][128] @ W[128][NOUT])   (dis pre-folded for gather)
// MODE 0: A_eff = A; MODE 1: A_eff = relu(A*sc+sh)+res, store xout; MODE 2: no store.
// BN scale/shift computed per-block from g_stats[SBUF].
template <int NOUT, int MODE, int SBUF>
__global__ void __launch_bounds__(256)
k_mgemm(const float* __restrict__ A, const float* __restrict__ W,
        float* __restrict__ C, const float* __restrict__ res,
        float* __restrict__ xout, const float* __restrict__ gvec,
        const float* __restrict__ bevec) {
    constexpr int WN = NOUT / 4;
    constexpr int NA = WN / 8;
    constexpr int ASTR = 132;
    constexpr int WSTR = NOUT + 8;
    extern __shared__ float sm[];
    float* As = sm;
    float* Ws = sm + 64 * ASTR;
    __shared__ float bnsc[128], bnsh[128];

    const int t = threadIdx.x;
    const int lane = t & 31, wid = t >> 5;
    const int row0 = blockIdx.x * 64;

    if constexpr (MODE >= 1) {
        if (t < 128) {
            float mu = g_stats[SBUF * 256 + t] * (1.0f / NN);
            float var = g_stats[SBUF * 256 + 128 + t] * (1.0f / NN) - mu * mu;
            float sc = gvec[t] * rsqrtf(var + BN_EPS);
            bnsc[t] = sc;
            bnsh[t] = bevec[t] - mu * sc;
        }
        __syncthreads();
    }

    // ---- fill A tile [64 x 128] with fused pre-op ----
#pragma unroll
    for (int i = 0; i < 8; i++) {
        int idx = t + i * 256;
        int r = idx >> 5;
        int c = (idx & 31) * 4;
        int row = row0 + r;
        float4 v = make_float4(0.f, 0.f, 0.f, 0.f);
        if (row < NN) {
            v = *(const float4*)&A[row * 128 + c];
            if constexpr (MODE >= 1) {
                float4 sc = *(const float4*)&bnsc[c];
                float4 sh = *(const float4*)&bnsh[c];
                float4 rr = *(const float4*)&res[row * 128 + c];
                v.x = fmaxf(fmaf(v.x, sc.x, sh.x), 0.f) + rr.x;
                v.y = fmaxf(fmaf(v.y, sc.y, sh.y), 0.f) + rr.y;
                v.z = fmaxf(fmaf(v.z, sc.z, sh.z), 0.f) + rr.z;
                v.w = fmaxf(fmaf(v.w, sc.w, sh.w), 0.f) + rr.w;
                if constexpr (MODE == 1)
                    *(float4*)&xout[row * 128 + c] = v;
            }
        }
        *(float4*)&As[r * ASTR + c] = v;
    }
    // ---- fill W [128 x NOUT] ----
#pragma unroll
    for (int i = 0; i < NOUT / 8; i++) {
        int idx = t + i * 256;
        int k = idx / (NOUT / 4);
        int n = (idx % (NOUT / 4)) * 4;
        float4 v = *(const float4*)&W[k * NOUT + n];
        *(float4*)&Ws[k * WSTR + n] = v;
    }
    __syncthreads();

    float acc[2][NA][4];
#pragma unroll
    for (int ma = 0; ma < 2; ma++)
#pragma unroll
        for (int na = 0; na < NA; na++)
#pragma unroll
            for (int j = 0; j < 4; j++) acc[ma][na][j] = 0.f;

    const int fr = lane >> 2;
    const int fc = lane & 3;
    const int mrow = (wid & 1) * 32;
    const int ncol = (wid >> 1) * WN;

#pragma unroll
    for (int ks = 0; ks < 16; ks++) {
        const int k0 = ks * 8;
        uint32_t ah[2][4], al[2][4];
#pragma unroll
        for (int ma = 0; ma < 2; ma++) {
            int rb = mrow + ma * 16 + fr;
            split_tf32(As[rb * ASTR + k0 + fc],            ah[ma][0], al[ma][0]);
            split_tf32(As[(rb + 8) * ASTR + k0 + fc],      ah[ma][1], al[ma][1]);
            split_tf32(As[rb * ASTR + k0 + fc + 4],        ah[ma][2], al[ma][2]);
            split_tf32(As[(rb + 8) * ASTR + k0 + fc + 4],  ah[ma][3], al[ma][3]);
        }
        uint32_t bh[NA][2], bl[NA][2];
#pragma unroll
        for (int na = 0; na < NA; na++) {
            int cb = ncol + na * 8 + fr;
            split_tf32(Ws[(k0 + fc) * WSTR + cb],       bh[na][0], bl[na][0]);
            split_tf32(Ws[(k0 + fc + 4) * WSTR + cb],   bh[na][1], bl[na][1]);
        }
#pragma unroll
        for (int ma = 0; ma < 2; ma++)
#pragma unroll
            for (int na = 0; na < NA; na++) {
                mma8(acc[ma][na], ah[ma], bh[na]);
                mma8(acc[ma][na], ah[ma], bl[na]);
                mma8(acc[ma][na], al[ma], bh[na]);
            }
    }

    // ---- epilogue: scale by dis[row], direct stores ----
#pragma unroll
    for (int ma = 0; ma < 2; ma++) {
        int r0 = row0 + mrow + ma * 16 + fr;
        float d0 = (r0 < NN) ? g_dis[r0] : 0.f;
        float d1 = (r0 + 8 < NN) ? g_dis[r0 + 8] : 0.f;
#pragma unroll
        for (int na = 0; na < NA; na++) {
            int cc = ncol + na * 8 + fc * 2;
            if (r0 < NN)
                *(float2*)&C[r0 * NOUT + cc] =
                    make_float2(acc[ma][na][0] * d0, acc[ma][na][1] * d0);
            if (r0 + 8 < NN)
                *(float2*)&C[(r0 + 8) * NOUT + cc] =
                    make_float2(acc[ma][na][2] * d1, acc[ma][na][3] * d1);
        }
    }
    // zero the dummy pad row (index NN) for the gather
    if (blockIdx.x == 0 && t < NOUT) C[NN * NOUT + t] = 0.f;
}

// ---------------- CSR gather (128ch): agg[d] = dis[d]*(sum h'[s] + h'[d]) + b
// h' is pre-scaled by dis. Fused BN-stat accumulation into g_stats[SBUF].
template <int SBUF>
__global__ void k_gather128(const float* __restrict__ h, float* __restrict__ agg,
                            const float* __restrict__ b) {
    __shared__ float ssum[128], ssum2[128];
    int t = threadIdx.x;
    if (t < 128) { ssum[t] = 0.f; ssum2[t] = 0.f; }
    int w = t >> 5, lane = t & 31;
    int d = blockIdx.x * 8 + w;
    float4 out;
    bool valid = d < NN;
    if (valid) {
        float disd = g_dis[d];
        int j = g_rowstart[d];
        int end = g_rowstart[d + 1];
        float4 acc = *(const float4*)&h[d * 128 + lane * 4];   // self term h'[d]
        const int* cs = (const int*)g_csrc4;
        for (; j < end; j += 4) {
            int4 s4 = *(const int4*)&cs[j];
            float4 v0 = *(const float4*)&h[s4.x * 128 + lane * 4];
            float4 v1 = *(const float4*)&h[s4.y * 128 + lane * 4];
            float4 v2 = *(const float4*)&h[s4.z * 128 + lane * 4];
            float4 v3 = *(const float4*)&h[s4.w * 128 + lane * 4];
            acc.x += (v0.x + v1.x) + (v2.x + v3.x);
            acc.y += (v0.y + v1.y) + (v2.y + v3.y);
            acc.z += (v0.z + v1.z) + (v2.z + v3.z);
            acc.w += (v0.w + v1.w) + (v2.w + v3.w);
        }
        float4 bv = *(const float4*)&b[lane * 4];
        out.x = fmaf(acc.x, disd, bv.x);
        out.y = fmaf(acc.y, disd, bv.y);
        out.z = fmaf(acc.z, disd, bv.z);
        out.w = fmaf(acc.w, disd, bv.w);
        *(float4*)&agg[d * 128 + lane * 4] = out;
    }
    __syncthreads();
    if (valid) {
        int c = lane * 4;
        atomicAdd(&ssum[c + 0], out.x);  atomicAdd(&ssum2[c + 0], out.x * out.x);
        atomicAdd(&ssum[c + 1], out.y);  atomicAdd(&ssum2[c + 1], out.y * out.y);
        atomicAdd(&ssum[c + 2], out.z);  atomicAdd(&ssum2[c + 2], out.z * out.z);
        atomicAdd(&ssum[c + 3], out.w);  atomicAdd(&ssum2[c + 3], out.w * out.w);
    }
    __syncthreads();
    if (t < 128) {
        atomicAdd(&g_stats[SBUF * 256 + t], ssum[t]);
        atomicAdd(&g_stats[SBUF * 256 + 128 + t], ssum2[t]);
    }
}

// ---------------- final gather (32ch) fused with log_softmax ----------------
__global__ void k_gather32_lsm(const float* __restrict__ h, float* __restrict__ out,
                               const float* __restrict__ b) {
    int t = threadIdx.x;
    int w = t >> 5, lane = t & 31;
    int d = blockIdx.x * 8 + w;
    if (d >= NN) return;
    float disd = g_dis[d];
    int j = g_rowstart[d];
    int end = g_rowstart[d + 1];
    float acc = h[d * 32 + lane];                  // self term h'[d]
    const int* cs = (const int*)g_csrc4;
    for (; j < end; j += 4) {
        int4 s4 = *(const int4*)&cs[j];
        float v0 = h[s4.x * 32 + lane];
        float v1 = h[s4.y * 32 + lane];
        float v2 = h[s4.z * 32 + lane];
        float v3 = h[s4.w * 32 + lane];
        acc += (v0 + v1) + (v2 + v3);
    }
    float logit = fmaf(acc, disd, b[lane]);
    float m = logit;
#pragma unroll
    for (int o = 16; o > 0; o >>= 1) m = fmaxf(m, __shfl_xor_sync(0xffffffffu, m, o));
    float e = __expf(logit - m);
    float s = e;
#pragma unroll
    for (int o = 16; o > 0; o >>= 1) s += __shfl_xor_sync(0xffffffffu, s, o);
    out[d * 32 + lane] = logit - m - logf(s);
}

// ---------------- launch ----------------
extern "C" void kernel_launch(void* const* d_in, const int* in_sizes, int n_in,
                              void* d_out, int out_size) {
    const float* x   = (const float*)d_in[0];
    const void*  ei  = d_in[1];
    const float* W0  = (const float*)d_in[2];
    const float* b0  = (const float*)d_in[3];
    const float* g0  = (const float*)d_in[4];
    const float* be0 = (const float*)d_in[5];
    const float* W1  = (const float*)d_in[6];
    const float* b1  = (const float*)d_in[7];
    const float* g1  = (const float*)d_in[8];
    const float* be1 = (const float*)d_in[9];
    const float* W2  = (const float*)d_in[10];
    const float* b2  = (const float*)d_in[11];
    float* out = (float*)d_out;

    float *p_h, *p_agg, *p_x;
    cudaGetSymbolAddress((void**)&p_h, g_h);
    cudaGetSymbolAddress((void**)&p_agg, g_agg);
    cudaGetSymbolAddress((void**)&p_x, g_x);

    const int nodeBlocks = (NN + 255) / 256;
    const int edgeBlocks = (NE + 255) / 256;
    const int gatherBlocks = (NN + 7) / 8;
    const int mgemmBlocks = (NN + 63) / 64;

    const int SM128 = (64 * 132 + 128 * 136) * 4; // 103424
    const int SM32  = (64 * 132 + 128 * 40) * 4;  // 54272
    cudaFuncSetAttribute(k_mgemm<128, 0, 0>, cudaFuncAttributeMaxDynamicSharedMemorySize, SM128);
    cudaFuncSetAttribute(k_mgemm<128, 1, 0>, cudaFuncAttributeMaxDynamicSharedMemorySize, SM128);
    cudaFuncSetAttribute(k_mgemm<32, 2, 1>,  cudaFuncAttributeMaxDynamicSharedMemorySize, SM32);

    // graph preprocessing: degrees -> padded CSR
    k_init0<<<nodeBlocks, 256>>>((const int*)ei);
    k_deg<<<edgeBlocks, 256>>>(ei);
    k_scan1<<<NB1, 1024>>>();
    k_scan2<<<1, 64>>>();
    k_scan3<<<nodeBlocks, 256>>>();
    k_fill<<<edgeBlocks, 256>>>(ei);
    k_pad<<<nodeBlocks, 256>>>();

    // ---- layer 0 ----
    k_mgemm<128, 0, 0><<<mgemmBlocks, 256, SM128>>>(x, W0, p_h, nullptr, nullptr, nullptr, nullptr);
    k_gather128<0><<<gatherBlocks, 256>>>(p_h, p_agg, b0);

    // ---- layer 1 ----
    k_mgemm<128, 1, 0><<<mgemmBlocks, 256, SM128>>>(p_agg, W1, p_h, x, p_x, g0, be0);
    k_gather128<1><<<gatherBlocks, 256>>>(p_h, p_agg, b1);

    // ---- final conv + fused log_softmax ----
    k_mgemm<32, 2, 1><<<mgemmBlocks, 256, SM32>>>(p_agg, W2, p_h, p_x, nullptr, g1, be1);
    k_gather32_lsm<<<gatherBlocks, 256>>>(p_h, out, b2);
}

// round 6
// speedup vs baseline: 1.8764x; 1.3581x over previous
#include <cuda_runtime.h>
#include <cuda_fp16.h>
#include <cstdint>

#define NN 50000
#define NE 800000
#define NB1 49            // ceil(NN/1024)
#define BN_EPS 1e-5f
#define CSRC_CAP (NE + 4 * NN)   // padded CSR capacity

// ---------------- scratch (static device globals; no allocation) ----------------
__device__ int    g_is64;
__device__ int    g_deg[NN];
__device__ int    g_rowstart[NN + 1];
__device__ int    g_cursor[NN];
__device__ int4   g_csrc4[CSRC_CAP / 4];
__device__ int    g_bsum[NB1];
__device__ float  g_dis[NN];
__device__ __half g_h16[(NN + 1) * 128];   // fp16 feature stream (+ zero dummy row)
__device__ float  g_h32[(NN + 1) * 32];    // fp32 final-layer stream
__device__ float  g_agg[NN * 128];
__device__ float  g_x[NN * 128];
__device__ float  g_stats[512];            // two buffers of 256 (sum|sumsq)

// ---------------- helpers ----------------
__device__ __forceinline__ uint32_t tf32_hi(float x) {
    uint32_t u;
    asm("cvt.rna.tf32.f32 %0, %1;" : "=r"(u) : "f"(x));
    return u;
}
__device__ __forceinline__ void split_tf32(float v, uint32_t& hi, uint32_t& lo) {
    hi = tf32_hi(v);
    lo = tf32_hi(v - __uint_as_float(hi));
}
__device__ __forceinline__ void mma8(float* d, const uint32_t* a, const uint32_t* b) {
    asm volatile(
        "mma.sync.aligned.m16n8k8.row.col.f32.tf32.tf32.f32 "
        "{%0,%1,%2,%3}, {%4,%5,%6,%7}, {%8,%9}, {%0,%1,%2,%3};"
        : "+f"(d[0]), "+f"(d[1]), "+f"(d[2]), "+f"(d[3])
        : "r"(a[0]), "r"(a[1]), "r"(a[2]), "r"(a[3]), "r"(b[0]), "r"(b[1]));
}

// ---------------- init: zero degrees + int64/int32 detect ----------------
__global__ void k_init0(const int* __restrict__ ei32) {
    int i = blockIdx.x * 256 + threadIdx.x;
    if (i < NN) g_deg[i] = 0;
    if (blockIdx.x == 0 && threadIdx.x == 0) {
        int all0 = 1;
#pragma unroll
        for (int j = 0; j < 64; j++) all0 &= (ei32[2 * j + 1] == 0);
        g_is64 = all0;
    }
}

__global__ void k_deg(const void* __restrict__ ei) {
    int e = blockIdx.x * 256 + threadIdx.x;
    if (e >= NE) return;
    int d = g_is64 ? (int)((const long long*)ei)[NE + e]
                   : ((const int*)ei)[NE + e];
    atomicAdd(&g_deg[d], 1);
}

// ---------------- CSR build (padded degrees, multiple of 4) ----------------
__global__ void k_scan1() {
    __shared__ int sd[1024];
    int t = threadIdx.x;
    int i = blockIdx.x * 1024 + t;
    int v = (i < NN) ? ((g_deg[i] + 3) & ~3) : 0;
    sd[t] = v;
    __syncthreads();
#pragma unroll
    for (int off = 1; off < 1024; off <<= 1) {
        int x = (t >= off) ? sd[t - off] : 0;
        __syncthreads();
        sd[t] += x;
        __syncthreads();
    }
    if (i < NN) g_rowstart[i] = sd[t] - v;
    if (t == 1023) g_bsum[blockIdx.x] = sd[1023];
}

// scan2 folded in: each block recomputes its 1024-chunk's global offset (<=48 adds).
__global__ void k_scan3() {
    __shared__ int boff_s;
    int t = threadIdx.x;
    int i = blockIdx.x * 256 + t;
    if (t == 0) {
        int chunk = (blockIdx.x * 256) >> 10;
        int s = 0;
        for (int j = 0; j < chunk; j++) s += g_bsum[j];
        boff_s = s;
    }
    if (blockIdx.x == 0 && t == 32) {
        int s = 0;
        for (int j = 0; j < NB1; j++) s += g_bsum[j];
        g_rowstart[NN] = s;                 // sentinel (padded total)
    }
    if (i < 512) g_stats[i] = 0.f;          // zero both BN stat buffers
    __syncthreads();
    if (i >= NN) return;
    int st = g_rowstart[i] + boff_s;
    g_rowstart[i] = st;
    g_cursor[i] = st;
    g_dis[i] = rsqrtf((float)g_deg[i] + 1.0f);
}

__global__ void k_fill(const void* __restrict__ ei) {
    int e = blockIdx.x * 256 + threadIdx.x;
    if (e >= NE) return;
    int s, d;
    if (g_is64) {
        const long long* p = (const long long*)ei;
        s = (int)p[e]; d = (int)p[NE + e];
    } else {
        const int* p = (const int*)ei;
        s = p[e]; d = p[NE + e];
    }
    int pos = atomicAdd(&g_cursor[d], 1);
    ((int*)g_csrc4)[pos] = s;
}

__global__ void k_pad() {
    int i = blockIdx.x * 256 + threadIdx.x;
    if (i >= NN) return;
    int p = g_cursor[i];
    int e = g_rowstart[i + 1];
    int* cs = (int*)g_csrc4;
    for (; p < e; p++) cs[p] = NN;          // dummy -> zero row
}

// ---------------- 3xTF32 warp-MMA GEMM ----------------
// C[N][NOUT] = dis[row] * (A_eff[N][128] @ W[128][NOUT])
// MODE 0: A_eff = A; MODE 1: A_eff = relu(A*sc+sh)+res, store xout; MODE 2: no store.
// O16: store C as fp16 (half2), else fp32.
template <int NOUT, int MODE, int SBUF, int O16>
__global__ void __launch_bounds__(256)
k_mgemm(const float* __restrict__ A, const float* __restrict__ W,
        void* __restrict__ Cv, const float* __restrict__ res,
        float* __restrict__ xout, const float* __restrict__ gvec,
        const float* __restrict__ bevec) {
    constexpr int WN = NOUT / 4;
    constexpr int NA = WN / 8;
    constexpr int ASTR = 132;
    constexpr int WSTR = NOUT + 8;
    extern __shared__ float sm[];
    float* As = sm;
    float* Ws = sm + 64 * ASTR;
    __shared__ float bnsc[128], bnsh[128];

    const int t = threadIdx.x;
    const int lane = t & 31, wid = t >> 5;
    const int row0 = blockIdx.x * 64;

    if constexpr (MODE >= 1) {
        if (t < 128) {
            float mu = g_stats[SBUF * 256 + t] * (1.0f / NN);
            float var = g_stats[SBUF * 256 + 128 + t] * (1.0f / NN) - mu * mu;
            float sc = gvec[t] * rsqrtf(var + BN_EPS);
            bnsc[t] = sc;
            bnsh[t] = bevec[t] - mu * sc;
        }
        __syncthreads();
    }

    // ---- fill A tile [64 x 128] with fused pre-op ----
#pragma unroll
    for (int i = 0; i < 8; i++) {
        int idx = t + i * 256;
        int r = idx >> 5;
        int c = (idx & 31) * 4;
        int row = row0 + r;
        float4 v = make_float4(0.f, 0.f, 0.f, 0.f);
        if (row < NN) {
            v = *(const float4*)&A[row * 128 + c];
            if constexpr (MODE >= 1) {
                float4 sc = *(const float4*)&bnsc[c];
                float4 sh = *(const float4*)&bnsh[c];
                float4 rr = *(const float4*)&res[row * 128 + c];
                v.x = fmaxf(fmaf(v.x, sc.x, sh.x), 0.f) + rr.x;
                v.y = fmaxf(fmaf(v.y, sc.y, sh.y), 0.f) + rr.y;
                v.z = fmaxf(fmaf(v.z, sc.z, sh.z), 0.f) + rr.z;
                v.w = fmaxf(fmaf(v.w, sc.w, sh.w), 0.f) + rr.w;
                if constexpr (MODE == 1)
                    *(float4*)&xout[row * 128 + c] = v;
            }
        }
        *(float4*)&As[r * ASTR + c] = v;
    }
    // ---- fill W [128 x NOUT] ----
#pragma unroll
    for (int i = 0; i < NOUT / 8; i++) {
        int idx = t + i * 256;
        int k = idx / (NOUT / 4);
        int n = (idx % (NOUT / 4)) * 4;
        float4 v = *(const float4*)&W[k * NOUT + n];
        *(float4*)&Ws[k * WSTR + n] = v;
    }
    __syncthreads();

    float acc[2][NA][4];
#pragma unroll
    for (int ma = 0; ma < 2; ma++)
#pragma unroll
        for (int na = 0; na < NA; na++)
#pragma unroll
            for (int j = 0; j < 4; j++) acc[ma][na][j] = 0.f;

    const int fr = lane >> 2;
    const int fc = lane & 3;
    const int mrow = (wid & 1) * 32;
    const int ncol = (wid >> 1) * WN;

#pragma unroll
    for (int ks = 0; ks < 16; ks++) {
        const int k0 = ks * 8;
        uint32_t ah[2][4], al[2][4];
#pragma unroll
        for (int ma = 0; ma < 2; ma++) {
            int rb = mrow + ma * 16 + fr;
            split_tf32(As[rb * ASTR + k0 + fc],            ah[ma][0], al[ma][0]);
            split_tf32(As[(rb + 8) * ASTR + k0 + fc],      ah[ma][1], al[ma][1]);
            split_tf32(As[rb * ASTR + k0 + fc + 4],        ah[ma][2], al[ma][2]);
            split_tf32(As[(rb + 8) * ASTR + k0 + fc + 4],  ah[ma][3], al[ma][3]);
        }
        uint32_t bh[NA][2], bl[NA][2];
#pragma unroll
        for (int na = 0; na < NA; na++) {
            int cb = ncol + na * 8 + fr;
            split_tf32(Ws[(k0 + fc) * WSTR + cb],       bh[na][0], bl[na][0]);
            split_tf32(Ws[(k0 + fc + 4) * WSTR + cb],   bh[na][1], bl[na][1]);
        }
#pragma unroll
        for (int ma = 0; ma < 2; ma++)
#pragma unroll
            for (int na = 0; na < NA; na++) {
                mma8(acc[ma][na], ah[ma], bh[na]);
                mma8(acc[ma][na], ah[ma], bl[na]);
                mma8(acc[ma][na], al[ma], bh[na]);
            }
    }

    // ---- epilogue: scale by dis[row], store fp16 or fp32 ----
#pragma unroll
    for (int ma = 0; ma < 2; ma++) {
        int r0 = row0 + mrow + ma * 16 + fr;
        float d0 = (r0 < NN) ? g_dis[r0] : 0.f;
        float d1 = (r0 + 8 < NN) ? g_dis[r0 + 8] : 0.f;
#pragma unroll
        for (int na = 0; na < NA; na++) {
            int cc = ncol + na * 8 + fc * 2;
            if constexpr (O16) {
                __half* C = (__half*)Cv;
                if (r0 < NN)
                    *(__half2*)&C[r0 * NOUT + cc] =
                        __floats2half2_rn(acc[ma][na][0] * d0, acc[ma][na][1] * d0);
                if (r0 + 8 < NN)
                    *(__half2*)&C[(r0 + 8) * NOUT + cc] =
                        __floats2half2_rn(acc[ma][na][2] * d1, acc[ma][na][3] * d1);
            } else {
                float* C = (float*)Cv;
                if (r0 < NN)
                    *(float2*)&C[r0 * NOUT + cc] =
                        make_float2(acc[ma][na][0] * d0, acc[ma][na][1] * d0);
                if (r0 + 8 < NN)
                    *(float2*)&C[(r0 + 8) * NOUT + cc] =
                        make_float2(acc[ma][na][2] * d1, acc[ma][na][3] * d1);
            }
        }
    }
    // zero the dummy pad row (index NN) for the gather
    if (blockIdx.x == 0 && t < NOUT) {
        if constexpr (O16) ((__half*)Cv)[NN * NOUT + t] = __float2half(0.f);
        else               ((float*)Cv)[NN * NOUT + t] = 0.f;
    }
}

// ---------------- CSR gather (128ch, fp16 in / fp32 out) ----------------
// agg[d] = dis[d]*(sum h'[s] + h'[d]) + b ; fused BN stats (no smem atomics).
template <int SBUF>
__global__ void k_gather128(const __half* __restrict__ h, float* __restrict__ agg,
                            const float* __restrict__ b) {
    __shared__ float ssum[8][128], ssum2[8][128];
    int t = threadIdx.x;
    int w = t >> 5, lane = t & 31;
    int d = blockIdx.x * 8 + w;
    float4 out = make_float4(0.f, 0.f, 0.f, 0.f);
    bool valid = d < NN;
    if (valid) {
        float disd = g_dis[d];
        int j = g_rowstart[d];
        int end = g_rowstart[d + 1];
        // self term
        uint2 sv = *(const uint2*)&h[d * 128 + lane * 4];
        float2 f0 = __half22float2(*(__half2*)&sv.x);
        float2 f1 = __half22float2(*(__half2*)&sv.y);
        float4 acc = make_float4(f0.x, f0.y, f1.x, f1.y);
        const int* cs = (const int*)g_csrc4;
        for (; j < end; j += 4) {
            int4 s4 = *(const int4*)&cs[j];
            uint2 v0 = *(const uint2*)&h[s4.x * 128 + lane * 4];
            uint2 v1 = *(const uint2*)&h[s4.y * 128 + lane * 4];
            uint2 v2 = *(const uint2*)&h[s4.z * 128 + lane * 4];
            uint2 v3 = *(const uint2*)&h[s4.w * 128 + lane * 4];
            float2 a0 = __half22float2(*(__half2*)&v0.x), a1 = __half22float2(*(__half2*)&v0.y);
            float2 b0 = __half22float2(*(__half2*)&v1.x), b1 = __half22float2(*(__half2*)&v1.y);
            float2 c0 = __half22float2(*(__half2*)&v2.x), c1 = __half22float2(*(__half2*)&v2.y);
            float2 d0 = __half22float2(*(__half2*)&v3.x), d1 = __half22float2(*(__half2*)&v3.y);
            acc.x += (a0.x + b0.x) + (c0.x + d0.x);
            acc.y += (a0.y + b0.y) + (c0.y + d0.y);
            acc.z += (a1.x + b1.x) + (c1.x + d1.x);
            acc.w += (a1.y + b1.y) + (c1.y + d1.y);
        }
        float4 bv = *(const float4*)&b[lane * 4];
        out.x = fmaf(acc.x, disd, bv.x);
        out.y = fmaf(acc.y, disd, bv.y);
        out.z = fmaf(acc.z, disd, bv.z);
        out.w = fmaf(acc.w, disd, bv.w);
        *(float4*)&agg[d * 128 + lane * 4] = out;
    }
    // BN stats: single-writer per-warp partials, tree reduce, 256 global REDs/block
    int c = lane * 4;
    ssum[w][c + 0] = out.x;  ssum2[w][c + 0] = out.x * out.x;
    ssum[w][c + 1] = out.y;  ssum2[w][c + 1] = out.y * out.y;
    ssum[w][c + 2] = out.z;  ssum2[w][c + 2] = out.z * out.z;
    ssum[w][c + 3] = out.w;  ssum2[w][c + 3] = out.w * out.w;
    __syncthreads();
    if (t < 128) {
        float s = 0.f, s2 = 0.f;
#pragma unroll
        for (int ww = 0; ww < 8; ww++) { s += ssum[ww][t]; s2 += ssum2[ww][t]; }
        atomicAdd(&g_stats[SBUF * 256 + t], s);
        atomicAdd(&g_stats[SBUF * 256 + 128 + t], s2);
    }
}

// ---------------- final gather (32ch fp32) fused with log_softmax ----------------
__global__ void k_gather32_lsm(const float* __restrict__ h, float* __restrict__ out,
                               const float* __restrict__ b) {
    int t = threadIdx.x;
    int w = t >> 5, lane = t & 31;
    int d = blockIdx.x * 8 + w;
    if (d >= NN) return;
    float disd = g_dis[d];
    int j = g_rowstart[d];
    int end = g_rowstart[d + 1];
    float acc = h[d * 32 + lane];
    const int* cs = (const int*)g_csrc4;
    for (; j < end; j += 4) {
        int4 s4 = *(const int4*)&cs[j];
        float v0 = h[s4.x * 32 + lane];
        float v1 = h[s4.y * 32 + lane];
        float v2 = h[s4.z * 32 + lane];
        float v3 = h[s4.w * 32 + lane];
        acc += (v0 + v1) + (v2 + v3);
    }
    float logit = fmaf(acc, disd, b[lane]);
    float m = logit;
#pragma unroll
    for (int o = 16; o > 0; o >>= 1) m = fmaxf(m, __shfl_xor_sync(0xffffffffu, m, o));
    float e = __expf(logit - m);
    float s = e;
#pragma unroll
    for (int o = 16; o > 0; o >>= 1) s += __shfl_xor_sync(0xffffffffu, s, o);
    out[d * 32 + lane] = logit - m - logf(s);
}

// ---------------- launch ----------------
extern "C" void kernel_launch(void* const* d_in, const int* in_sizes, int n_in,
                              void* d_out, int out_size) {
    const float* x   = (const float*)d_in[0];
    const void*  ei  = d_in[1];
    const float* W0  = (const float*)d_in[2];
    const float* b0  = (const float*)d_in[3];
    const float* g0  = (const float*)d_in[4];
    const float* be0 = (const float*)d_in[5];
    const float* W1  = (const float*)d_in[6];
    const float* b1  = (const float*)d_in[7];
    const float* g1  = (const float*)d_in[8];
    const float* be1 = (const float*)d_in[9];
    const float* W2  = (const float*)d_in[10];
    const float* b2  = (const float*)d_in[11];
    float* out = (float*)d_out;

    __half* p_h16; float *p_h32, *p_agg, *p_x;
    cudaGetSymbolAddress((void**)&p_h16, g_h16);
    cudaGetSymbolAddress((void**)&p_h32, g_h32);
    cudaGetSymbolAddress((void**)&p_agg, g_agg);
    cudaGetSymbolAddress((void**)&p_x, g_x);

    const int nodeBlocks = (NN + 255) / 256;
    const int edgeBlocks = (NE + 255) / 256;
    const int gatherBlocks = (NN + 7) / 8;
    const int mgemmBlocks = (NN + 63) / 64;

    const int SM128 = (64 * 132 + 128 * 136) * 4; // 103424
    const int SM32  = (64 * 132 + 128 * 40) * 4;  // 54272
    cudaFuncSetAttribute(k_mgemm<128, 0, 0, 1>, cudaFuncAttributeMaxDynamicSharedMemorySize, SM128);
    cudaFuncSetAttribute(k_mgemm<128, 1, 0, 1>, cudaFuncAttributeMaxDynamicSharedMemorySize, SM128);
    cudaFuncSetAttribute(k_mgemm<32, 2, 1, 0>,  cudaFuncAttributeMaxDynamicSharedMemorySize, SM32);

    // graph preprocessing: degrees -> padded CSR
    k_init0<<<nodeBlocks, 256>>>((const int*)ei);
    k_deg<<<edgeBlocks, 256>>>(ei);
    k_scan1<<<NB1, 1024>>>();
    k_scan3<<<nodeBlocks, 256>>>();
    k_fill<<<edgeBlocks, 256>>>(ei);
    k_pad<<<nodeBlocks, 256>>>();

    // ---- layer 0 ----
    k_mgemm<128, 0, 0, 1><<<mgemmBlocks, 256, SM128>>>(x, W0, p_h16, nullptr, nullptr, nullptr, nullptr);
    k_gather128<0><<<gatherBlocks, 256>>>(p_h16, p_agg, b0);

    // ---- layer 1 ----
    k_mgemm<128, 1, 0, 1><<<mgemmBlocks, 256, SM128>>>(p_agg, W1, p_h16, x, p_x, g0, be0);
    k_gather128<1><<<gatherBlocks, 256>>>(p_h16, p_agg, b1);

    // ---- final conv + fused log_softmax ----
    k_mgemm<32, 2, 1, 0><<<mgemmBlocks, 256, SM32>>>(p_agg, W2, p_h32, p_x, nullptr, g1, be1);
    k_gather32_lsm<<<gatherBlocks, 256>>>(p_h32, out, b2);
}

// round 9
// speedup vs baseline: 1.8886x; 1.0065x over previous
#include <cuda_runtime.h>
#include <cuda_fp16.h>
#include <cstdint>

#define NN 50000
#define NE 800000
#define NB1 49            // ceil(NN/1024)
#define BN_EPS 1e-5f
#define CSRC_CAP (NE + 4 * NN)   // padded CSR capacity (ints)

// ---------------- scratch (static device globals; no allocation) ----------------
__device__ int    g_is64;
__device__ int    g_deg[NN];
__device__ int    g_rowstart[NN + 1];
__device__ int    g_cursor[NN];
__device__ int4   g_csrc4[CSRC_CAP / 4];
__device__ int    g_bsum[NB1];
__device__ float  g_dis[NN];
__device__ __half g_h16[(NN + 1) * 128];   // fp16 feature stream (+ zero dummy row)
__device__ float  g_agg[NN * 128];
__device__ float  g_x[NN * 128];
__device__ float  g_stats[512];            // two buffers of 256 (sum|sumsq)

// ---------------- helpers ----------------
__device__ __forceinline__ uint32_t tf32_hi(float x) {
    uint32_t u;
    asm("cvt.rna.tf32.f32 %0, %1;" : "=r"(u) : "f"(x));
    return u;
}
__device__ __forceinline__ void split_tf32(float v, uint32_t& hi, uint32_t& lo) {
    hi = tf32_hi(v);
    lo = tf32_hi(v - __uint_as_float(hi));
}
__device__ __forceinline__ void mma8(float* d, const uint32_t* a, const uint32_t* b) {
    asm volatile(
        "mma.sync.aligned.m16n8k8.row.col.f32.tf32.tf32.f32 "
        "{%0,%1,%2,%3}, {%4,%5,%6,%7}, {%8,%9}, {%0,%1,%2,%3};"
        : "+f"(d[0]), "+f"(d[1]), "+f"(d[2]), "+f"(d[3])
        : "r"(a[0]), "r"(a[1]), "r"(a[2]), "r"(a[3]), "r"(b[0]), "r"(b[1]));
}

// ---------------- init: zero degrees + prefill CSR pad + int64/int32 detect ------
__global__ void k_init0(const int* __restrict__ ei32) {
    int i = blockIdx.x * 256 + threadIdx.x;
    if (i < NN) g_deg[i] = 0;
    if (i < CSRC_CAP / 4) g_csrc4[i] = make_int4(NN, NN, NN, NN);  // dummy srcs
    if (i == 0) {
        int all0 = 1;
#pragma unroll
        for (int j = 0; j < 64; j++) all0 &= (ei32[2 * j + 1] == 0);
        g_is64 = all0;
    }
}

__global__ void k_deg(const void* __restrict__ ei) {
    int e = blockIdx.x * 256 + threadIdx.x;
    if (e >= NE) return;
    int d = g_is64 ? (int)((const long long*)ei)[NE + e]
                   : ((const int*)ei)[NE + e];
    atomicAdd(&g_deg[d], 1);
}

// ---------------- CSR build (padded degrees, multiple of 4) ----------------
__global__ void k_scan1() {
    __shared__ int sd[1024];
    int t = threadIdx.x;
    int i = blockIdx.x * 1024 + t;
    int v = (i < NN) ? ((g_deg[i] + 3) & ~3) : 0;
    sd[t] = v;
    __syncthreads();
#pragma unroll
    for (int off = 1; off < 1024; off <<= 1) {
        int x = (t >= off) ? sd[t - off] : 0;
        __syncthreads();
        sd[t] += x;
        __syncthreads();
    }
    if (i < NN) g_rowstart[i] = sd[t] - v;
    if (t == 1023) g_bsum[blockIdx.x] = sd[1023];
}

// scan2 folded in: parallel Hillis-Steele prefix over the 49 block sums.
__global__ void k_scan3() {
    __shared__ int sb[64];
    int t = threadIdx.x;
    int i = blockIdx.x * 256 + t;
    if (t < 64) sb[t] = (t < NB1) ? g_bsum[t] : 0;
    __syncthreads();
#pragma unroll
    for (int off = 1; off < 64; off <<= 1) {
        int x = (t < 64 && t >= off) ? sb[t - off] : 0;
        __syncthreads();
        if (t < 64) sb[t] += x;
        __syncthreads();
    }
    if (blockIdx.x == 0 && t == 0) g_rowstart[NN] = sb[NB1 - 1]; // sentinel
    if (i < 512) g_stats[i] = 0.f;          // zero both BN stat buffers
    if (i >= NN) return;
    int chunk = (blockIdx.x * 256) >> 10;
    int boff = (chunk == 0) ? 0 : sb[chunk - 1];
    int st = g_rowstart[i] + boff;
    g_rowstart[i] = st;
    g_cursor[i] = st;
    g_dis[i] = rsqrtf((float)g_deg[i] + 1.0f);
}

__global__ void k_fill(const void* __restrict__ ei) {
    int e = blockIdx.x * 256 + threadIdx.x;
    if (e >= NE) return;
    int s, d;
    if (g_is64) {
        const long long* p = (const long long*)ei;
        s = (int)p[e]; d = (int)p[NE + e];
    } else {
        const int* p = (const int*)ei;
        s = p[e]; d = p[NE + e];
    }
    int pos = atomicAdd(&g_cursor[d], 1);
    ((int*)g_csrc4)[pos] = s;
}

// ---------------- 3xTF32 warp-MMA GEMM ----------------
// C[N][NOUT] = dis[row] * (A_eff[N][128] @ W[128][NOUT]) stored fp16
// MODE 0: A_eff = A; MODE 1: A_eff = relu(A*sc+sh)+res, store xout; MODE 2: no store.
template <int NOUT, int MODE, int SBUF>
__global__ void __launch_bounds__(256)
k_mgemm(const float* __restrict__ A, const float* __restrict__ W,
        __half* __restrict__ C, const float* __restrict__ res,
        float* __restrict__ xout, const float* __restrict__ gvec,
        const float* __restrict__ bevec) {
    constexpr int WN = NOUT / 4;
    constexpr int NA = WN / 8;
    constexpr int ASTR = 132;
    constexpr int WSTR = NOUT + 8;
    extern __shared__ float sm[];
    float* As = sm;
    float* Ws = sm + 64 * ASTR;
    __shared__ float bnsc[128], bnsh[128];

    const int t = threadIdx.x;
    const int lane = t & 31, wid = t >> 5;
    const int row0 = blockIdx.x * 64;

    if constexpr (MODE >= 1) {
        if (t < 128) {
            float mu = g_stats[SBUF * 256 + t] * (1.0f / NN);
            float var = g_stats[SBUF * 256 + 128 + t] * (1.0f / NN) - mu * mu;
            float sc = gvec[t] * rsqrtf(var + BN_EPS);
            bnsc[t] = sc;
            bnsh[t] = bevec[t] - mu * sc;
        }
        __syncthreads();
    }

    // ---- fill A tile [64 x 128] with fused pre-op ----
#pragma unroll
    for (int i = 0; i < 8; i++) {
        int idx = t + i * 256;
        int r = idx >> 5;
        int c = (idx & 31) * 4;
        int row = row0 + r;
        float4 v = make_float4(0.f, 0.f, 0.f, 0.f);
        if (row < NN) {
            v = *(const float4*)&A[row * 128 + c];
            if constexpr (MODE >= 1) {
                float4 sc = *(const float4*)&bnsc[c];
                float4 sh = *(const float4*)&bnsh[c];
                float4 rr = *(const float4*)&res[row * 128 + c];
                v.x = fmaxf(fmaf(v.x, sc.x, sh.x), 0.f) + rr.x;
                v.y = fmaxf(fmaf(v.y, sc.y, sh.y), 0.f) + rr.y;
                v.z = fmaxf(fmaf(v.z, sc.z, sh.z), 0.f) + rr.z;
                v.w = fmaxf(fmaf(v.w, sc.w, sh.w), 0.f) + rr.w;
                if constexpr (MODE == 1)
                    *(float4*)&xout[row * 128 + c] = v;
            }
        }
        *(float4*)&As[r * ASTR + c] = v;
    }
    // ---- fill W [128 x NOUT] ----
#pragma unroll
    for (int i = 0; i < NOUT / 8; i++) {
        int idx = t + i * 256;
        int k = idx / (NOUT / 4);
        int n = (idx % (NOUT / 4)) * 4;
        float4 v = *(const float4*)&W[k * NOUT + n];
        *(float4*)&Ws[k * WSTR + n] = v;
    }
    __syncthreads();

    float acc[2][NA][4];
#pragma unroll
    for (int ma = 0; ma < 2; ma++)
#pragma unroll
        for (int na = 0; na < NA; na++)
#pragma unroll
            for (int j = 0; j < 4; j++) acc[ma][na][j] = 0.f;

    const int fr = lane >> 2;
    const int fc = lane & 3;
    const int mrow = (wid & 1) * 32;
    const int ncol = (wid >> 1) * WN;

#pragma unroll
    for (int ks = 0; ks < 16; ks++) {
        const int k0 = ks * 8;
        uint32_t ah[2][4], al[2][4];
#pragma unroll
        for (int ma = 0; ma < 2; ma++) {
            int rb = mrow + ma * 16 + fr;
            split_tf32(As[rb * ASTR + k0 + fc],            ah[ma][0], al[ma][0]);
            split_tf32(As[(rb + 8) * ASTR + k0 + fc],      ah[ma][1], al[ma][1]);
            split_tf32(As[rb * ASTR + k0 + fc + 4],        ah[ma][2], al[ma][2]);
            split_tf32(As[(rb + 8) * ASTR + k0 + fc + 4],  ah[ma][3], al[ma][3]);
        }
        uint32_t bh[NA][2], bl[NA][2];
#pragma unroll
        for (int na = 0; na < NA; na++) {
            int cb = ncol + na * 8 + fr;
            split_tf32(Ws[(k0 + fc) * WSTR + cb],       bh[na][0], bl[na][0]);
            split_tf32(Ws[(k0 + fc + 4) * WSTR + cb],   bh[na][1], bl[na][1]);
        }
#pragma unroll
        for (int ma = 0; ma < 2; ma++)
#pragma unroll
            for (int na = 0; na < NA; na++) {
                mma8(acc[ma][na], ah[ma], bh[na]);
                mma8(acc[ma][na], ah[ma], bl[na]);
                mma8(acc[ma][na], al[ma], bh[na]);
            }
    }

    // ---- epilogue: scale by dis[row], store fp16 ----
#pragma unroll
    for (int ma = 0; ma < 2; ma++) {
        int r0 = row0 + mrow + ma * 16 + fr;
        float d0 = (r0 < NN) ? g_dis[r0] : 0.f;
        float d1 = (r0 + 8 < NN) ? g_dis[r0 + 8] : 0.f;
#pragma unroll
        for (int na = 0; na < NA; na++) {
            int cc = ncol + na * 8 + fc * 2;
            if (r0 < NN)
                *(__half2*)&C[r0 * NOUT + cc] =
                    __floats2half2_rn(acc[ma][na][0] * d0, acc[ma][na][1] * d0);
            if (r0 + 8 < NN)
                *(__half2*)&C[(r0 + 8) * NOUT + cc] =
                    __floats2half2_rn(acc[ma][na][2] * d1, acc[ma][na][3] * d1);
        }
    }
    // zero the dummy pad row (index NN) for the gather
    if (blockIdx.x == 0 && t < NOUT) C[NN * NOUT + t] = __float2half(0.f);
}

// ---------------- CSR gather (128ch, fp16 in / fp32 out) ----------------
// agg[d] = dis[d]*(sum h'[s] + h'[d]) + b ; fused BN stats (no smem atomics).
template <int SBUF>
__global__ void k_gather128(const __half* __restrict__ h, float* __restrict__ agg,
                            const float* __restrict__ b) {
    __shared__ float ssum[8][128], ssum2[8][128];
    int t = threadIdx.x;
    int w = t >> 5, lane = t & 31;
    int d = blockIdx.x * 8 + w;
    float4 out = make_float4(0.f, 0.f, 0.f, 0.f);
    bool valid = d < NN;
    if (valid) {
        float disd = g_dis[d];
        int j = g_rowstart[d];
        int end = g_rowstart[d + 1];
        uint2 sv = *(const uint2*)&h[d * 128 + lane * 4];
        float2 f0 = __half22float2(*(__half2*)&sv.x);
        float2 f1 = __half22float2(*(__half2*)&sv.y);
        float4 acc = make_float4(f0.x, f0.y, f1.x, f1.y);
        const int* cs = (const int*)g_csrc4;
        for (; j < end; j += 4) {
            int4 s4 = *(const int4*)&cs[j];
            uint2 v0 = *(const uint2*)&h[s4.x * 128 + lane * 4];
            uint2 v1 = *(const uint2*)&h[s4.y * 128 + lane * 4];
            uint2 v2 = *(const uint2*)&h[s4.z * 128 + lane * 4];
            uint2 v3 = *(const uint2*)&h[s4.w * 128 + lane * 4];
            float2 a0 = __half22float2(*(__half2*)&v0.x), a1 = __half22float2(*(__half2*)&v0.y);
            float2 b0 = __half22float2(*(__half2*)&v1.x), b1 = __half22float2(*(__half2*)&v1.y);
            float2 c0 = __half22float2(*(__half2*)&v2.x), c1 = __half22float2(*(__half2*)&v2.y);
            float2 d0 = __half22float2(*(__half2*)&v3.x), d1 = __half22float2(*(__half2*)&v3.y);
            acc.x += (a0.x + b0.x) + (c0.x + d0.x);
            acc.y += (a0.y + b0.y) + (c0.y + d0.y);
            acc.z += (a1.x + b1.x) + (c1.x + d1.x);
            acc.w += (a1.y + b1.y) + (c1.y + d1.y);
        }
        float4 bv = *(const float4*)&b[lane * 4];
        out.x = fmaf(acc.x, disd, bv.x);
        out.y = fmaf(acc.y, disd, bv.y);
        out.z = fmaf(acc.z, disd, bv.z);
        out.w = fmaf(acc.w, disd, bv.w);
        *(float4*)&agg[d * 128 + lane * 4] = out;
    }
    int c = lane * 4;
    ssum[w][c + 0] = out.x;  ssum2[w][c + 0] = out.x * out.x;
    ssum[w][c + 1] = out.y;  ssum2[w][c + 1] = out.y * out.y;
    ssum[w][c + 2] = out.z;  ssum2[w][c + 2] = out.z * out.z;
    ssum[w][c + 3] = out.w;  ssum2[w][c + 3] = out.w * out.w;
    __syncthreads();
    if (t < 128) {
        float s = 0.f, s2 = 0.f;
#pragma unroll
        for (int ww = 0; ww < 8; ww++) { s += ssum[ww][t]; s2 += ssum2[ww][t]; }
        atomicAdd(&g_stats[SBUF * 256 + t], s);
        atomicAdd(&g_stats[SBUF * 256 + 128 + t], s2);
    }
}

// ---------------- final gather (32ch fp16) fused with log_softmax ----------------
__global__ void k_gather32_lsm(const __half* __restrict__ h, float* __restrict__ out,
                               const float* __restrict__ b) {
    int t = threadIdx.x;
    int w = t >> 5, lane = t & 31;
    int d = blockIdx.x * 8 + w;
    if (d >= NN) return;
    float disd = g_dis[d];
    int j = g_rowstart[d];
    int end = g_rowstart[d + 1];
    float acc = __half2float(h[d * 32 + lane]);
    const int* cs = (const int*)g_csrc4;
    for (; j < end; j += 4) {
        int4 s4 = *(const int4*)&cs[j];
        float v0 = __half2float(h[s4.x * 32 + lane]);
        float v1 = __half2float(h[s4.y * 32 + lane]);
        float v2 = __half2float(h[s4.z * 32 + lane]);
        float v3 = __half2float(h[s4.w * 32 + lane]);
        acc += (v0 + v1) + (v2 + v3);
    }
    float logit = fmaf(acc, disd, b[lane]);
    float m = logit;
#pragma unroll
    for (int o = 16; o > 0; o >>= 1) m = fmaxf(m, __shfl_xor_sync(0xffffffffu, m, o));
    float e = __expf(logit - m);
    float s = e;
#pragma unroll
    for (int o = 16; o > 0; o >>= 1) s += __shfl_xor_sync(0xffffffffu, s, o);
    out[d * 32 + lane] = logit - m - logf(s);
}

// ---------------- launch ----------------
extern "C" void kernel_launch(void* const* d_in, const int* in_sizes, int n_in,
                              void* d_out, int out_size) {
    const float* x   = (const float*)d_in[0];
    const void*  ei  = d_in[1];
    const float* W0  = (const float*)d_in[2];
    const float* b0  = (const float*)d_in[3];
    const float* g0  = (const float*)d_in[4];
    const float* be0 = (const float*)d_in[5];
    const float* W1  = (const float*)d_in[6];
    const float* b1  = (const float*)d_in[7];
    const float* g1  = (const float*)d_in[8];
    const float* be1 = (const float*)d_in[9];
    const float* W2  = (const float*)d_in[10];
    const float* b2  = (const float*)d_in[11];
    float* out = (float*)d_out;

    __half* p_h16; float *p_agg, *p_x;
    cudaGetSymbolAddress((void**)&p_h16, g_h16);
    cudaGetSymbolAddress((void**)&p_agg, g_agg);
    cudaGetSymbolAddress((void**)&p_x, g_x);

    const int initBlocks = (CSRC_CAP / 4 + 255) / 256;  // covers csrc prefill + deg zero
    const int nodeBlocks = (NN + 255) / 256;
    const int edgeBlocks = (NE + 255) / 256;
    const int gatherBlocks = (NN + 7) / 8;
    const int mgemmBlocks = (NN + 63) / 64;

    const int SM128 = (64 * 132 + 128 * 136) * 4; // 103424
    const int SM32  = (64 * 132 + 128 * 40) * 4;  // 54272
    cudaFuncSetAttribute(k_mgemm<128, 0, 0>, cudaFuncAttributeMaxDynamicSharedMemorySize, SM128);
    cudaFuncSetAttribute(k_mgemm<128, 1, 0>, cudaFuncAttributeMaxDynamicSharedMemorySize, SM128);
    cudaFuncSetAttribute(k_mgemm<32, 2, 1>,  cudaFuncAttributeMaxDynamicSharedMemorySize, SM32);

    // graph preprocessing: degrees -> padded CSR (pad slots prefilled in init0)
    k_init0<<<initBlocks, 256>>>((const int*)ei);
    k_deg<<<edgeBlocks, 256>>>(ei);
    k_scan1<<<NB1, 1024>>>();
    k_scan3<<<nodeBlocks, 256>>>();
    k_fill<<<edgeBlocks, 256>>>(ei);

    // ---- layer 0 ----
    k_mgemm<128, 0, 0><<<mgemmBlocks, 256, SM128>>>(x, W0, p_h16, nullptr, nullptr, nullptr, nullptr);
    k_gather128<0><<<gatherBlocks, 256>>>(p_h16, p_agg, b0);

    // ---- layer 1 ----
    k_mgemm<128, 1, 0><<<mgemmBlocks, 256, SM128>>>(p_agg, W1, p_h16, x, p_x, g0, be0);
    k_gather128<1><<<gatherBlocks, 256>>>(p_h16, p_agg, b1);

    // ---- final conv + fused log_softmax ----
    k_mgemm<32, 2, 1><<<mgemmBlocks, 256, SM32>>>(p_agg, W2, p_h16, p_x, nullptr, g1, be1);
    k_gather32_lsm<<<gatherBlocks, 256>>>(p_h16, out, b2);
}

// round 10
// speedup vs baseline: 2.0157x; 1.0673x over previous
#include <cuda_runtime.h>
#include <cuda_fp16.h>
#include <cstdint>

#define NN 50000
#define NE 800000
#define NB1 49            // ceil(NN/1024)
#define BN_EPS 1e-5f
#define CSRC_CAP (NE + 4 * NN)   // padded CSR capacity (ints)

// ---------------- scratch (static device globals; no allocation) ----------------
__device__ int    g_is64;
__device__ int    g_deg[NN];
__device__ int    g_rowstart[NN + 1];
__device__ int    g_cursor[NN];
__device__ int4   g_csrc4[CSRC_CAP / 4];
__device__ int    g_bsum[NB1];
__device__ float  g_dis[NN];
__device__ __half g_h16[(NN + 1) * 128];   // fp16 feature stream (+ zero dummy row)
__device__ __half g_agg16[NN * 128];       // fp16 aggregated stream
__device__ __half g_x16[NN * 128];         // fp16 residual stream (x1)
__device__ float  g_stats[512];            // two buffers of 256 (sum|sumsq)

// ---------------- helpers ----------------
__device__ __forceinline__ uint32_t tf32_hi(float x) {
    uint32_t u;
    asm("cvt.rna.tf32.f32 %0, %1;" : "=r"(u) : "f"(x));
    return u;
}
__device__ __forceinline__ void split_tf32(float v, uint32_t& hi, uint32_t& lo) {
    hi = tf32_hi(v);
    lo = tf32_hi(v - __uint_as_float(hi));
}
__device__ __forceinline__ void mma8(float* d, const uint32_t* a, const uint32_t* b) {
    asm volatile(
        "mma.sync.aligned.m16n8k8.row.col.f32.tf32.tf32.f32 "
        "{%0,%1,%2,%3}, {%4,%5,%6,%7}, {%8,%9}, {%0,%1,%2,%3};"
        : "+f"(d[0]), "+f"(d[1]), "+f"(d[2]), "+f"(d[3])
        : "r"(a[0]), "r"(a[1]), "r"(a[2]), "r"(a[3]), "r"(b[0]), "r"(b[1]));
}
__device__ __forceinline__ float4 ld_h4(const __half* p) {
    uint2 u = *(const uint2*)p;
    float2 a = __half22float2(*(__half2*)&u.x);
    float2 b = __half22float2(*(__half2*)&u.y);
    return make_float4(a.x, a.y, b.x, b.y);
}
__device__ __forceinline__ void st_h4(__half* p, float4 v) {
    __half2 o0 = __floats2half2_rn(v.x, v.y);
    __half2 o1 = __floats2half2_rn(v.z, v.w);
    uint2 u;
    u.x = *(uint32_t*)&o0;
    u.y = *(uint32_t*)&o1;
    *(uint2*)p = u;
}

// ---------------- init: zero degrees + prefill CSR pad + int64/int32 detect ------
__global__ void k_init0(const int* __restrict__ ei32) {
    int i = blockIdx.x * 256 + threadIdx.x;
    if (i < NN) g_deg[i] = 0;
    if (i < CSRC_CAP / 4) g_csrc4[i] = make_int4(NN, NN, NN, NN);  // dummy srcs
    if (i == 0) {
        int all0 = 1;
#pragma unroll
        for (int j = 0; j < 64; j++) all0 &= (ei32[2 * j + 1] == 0);
        g_is64 = all0;
    }
}

__global__ void k_deg(const void* __restrict__ ei) {
    int e = blockIdx.x * 256 + threadIdx.x;
    if (e >= NE) return;
    // int64 case: read only the low 4B word of dst
    int d = g_is64 ? ((const int*)ei)[2 * (NE + e)]
                   : ((const int*)ei)[NE + e];
    atomicAdd(&g_deg[d], 1);
}

// ---------------- dis + BN-stat zero (main-stream branch) ----------------
__global__ void k_dis() {
    int i = blockIdx.x * 256 + threadIdx.x;
    if (i < 512) g_stats[i] = 0.f;
    if (i < NN) g_dis[i] = rsqrtf((float)g_deg[i] + 1.0f);
}

// ---------------- CSR build (padded degrees, multiple of 4) ----------------
__global__ void k_scan1() {
    __shared__ int sd[1024];
    int t = threadIdx.x;
    int i = blockIdx.x * 1024 + t;
    int v = (i < NN) ? ((g_deg[i] + 3) & ~3) : 0;
    sd[t] = v;
    __syncthreads();
#pragma unroll
    for (int off = 1; off < 1024; off <<= 1) {
        int x = (t >= off) ? sd[t - off] : 0;
        __syncthreads();
        sd[t] += x;
        __syncthreads();
    }
    if (i < NN) g_rowstart[i] = sd[t] - v;
    if (t == 1023) g_bsum[blockIdx.x] = sd[1023];
}

// scan2 folded in: parallel Hillis-Steele prefix over the 49 block sums.
__global__ void k_scan3() {
    __shared__ int sb[64];
    int t = threadIdx.x;
    int i = blockIdx.x * 256 + t;
    if (t < 64) sb[t] = (t < NB1) ? g_bsum[t] : 0;
    __syncthreads();
#pragma unroll
    for (int off = 1; off < 64; off <<= 1) {
        int x = (t < 64 && t >= off) ? sb[t - off] : 0;
        __syncthreads();
        if (t < 64) sb[t] += x;
        __syncthreads();
    }
    if (blockIdx.x == 0 && t == 0) g_rowstart[NN] = sb[NB1 - 1]; // sentinel
    if (i >= NN) return;
    int chunk = (blockIdx.x * 256) >> 10;
    int boff = (chunk == 0) ? 0 : sb[chunk - 1];
    int st = g_rowstart[i] + boff;
    g_rowstart[i] = st;
    g_cursor[i] = st;
}

__global__ void k_fill(const void* __restrict__ ei) {
    int e = blockIdx.x * 256 + threadIdx.x;
    if (e >= NE) return;
    int s, d;
    if (g_is64) {
        const int* p = (const int*)ei;
        s = p[2 * e];
        d = p[2 * (NE + e)];
    } else {
        const int* p = (const int*)ei;
        s = p[e];
        d = p[NE + e];
    }
    int pos = atomicAdd(&g_cursor[d], 1);
    ((int*)g_csrc4)[pos] = s;
}

// ---------------- 3xTF32 warp-MMA GEMM ----------------
// C[N][NOUT] = dis[row] * (A_eff[N][128] @ W[128][NOUT]) stored fp16
// MODE 0: A_eff = A; MODE 1: A_eff = relu(A*sc+sh)+res, store xout fp16; MODE 2: no store.
// AIN16 / RES16: A / res streams are fp16.
template <int NOUT, int MODE, int SBUF, int AIN16, int RES16>
__global__ void __launch_bounds__(256)
k_mgemm(const void* __restrict__ Av, const float* __restrict__ W,
        __half* __restrict__ C, const void* __restrict__ resv,
        __half* __restrict__ xout, const float* __restrict__ gvec,
        const float* __restrict__ bevec) {
    constexpr int WN = NOUT / 4;
    constexpr int NA = WN / 8;
    constexpr int ASTR = 132;
    constexpr int WSTR = NOUT + 8;
    extern __shared__ float sm[];
    float* As = sm;
    float* Ws = sm + 64 * ASTR;
    __shared__ float bnsc[128], bnsh[128];

    const int t = threadIdx.x;
    const int lane = t & 31, wid = t >> 5;
    const int row0 = blockIdx.x * 64;

    if constexpr (MODE >= 1) {
        if (t < 128) {
            float mu = g_stats[SBUF * 256 + t] * (1.0f / NN);
            float var = g_stats[SBUF * 256 + 128 + t] * (1.0f / NN) - mu * mu;
            float sc = gvec[t] * rsqrtf(var + BN_EPS);
            bnsc[t] = sc;
            bnsh[t] = bevec[t] - mu * sc;
        }
        __syncthreads();
    }

    // ---- fill A tile [64 x 128] with fused pre-op ----
#pragma unroll
    for (int i = 0; i < 8; i++) {
        int idx = t + i * 256;
        int r = idx >> 5;
        int c = (idx & 31) * 4;
        int row = row0 + r;
        float4 v = make_float4(0.f, 0.f, 0.f, 0.f);
        if (row < NN) {
            if constexpr (AIN16) v = ld_h4(&((const __half*)Av)[row * 128 + c]);
            else                 v = *(const float4*)&((const float*)Av)[row * 128 + c];
            if constexpr (MODE >= 1) {
                float4 sc = *(const float4*)&bnsc[c];
                float4 sh = *(const float4*)&bnsh[c];
                float4 rr;
                if constexpr (RES16) rr = ld_h4(&((const __half*)resv)[row * 128 + c]);
                else                 rr = *(const float4*)&((const float*)resv)[row * 128 + c];
                v.x = fmaxf(fmaf(v.x, sc.x, sh.x), 0.f) + rr.x;
                v.y = fmaxf(fmaf(v.y, sc.y, sh.y), 0.f) + rr.y;
                v.z = fmaxf(fmaf(v.z, sc.z, sh.z), 0.f) + rr.z;
                v.w = fmaxf(fmaf(v.w, sc.w, sh.w), 0.f) + rr.w;
                if constexpr (MODE == 1)
                    st_h4(&xout[row * 128 + c], v);
            }
        }
        *(float4*)&As[r * ASTR + c] = v;
    }
    // ---- fill W [128 x NOUT] ----
#pragma unroll
    for (int i = 0; i < NOUT / 8; i++) {
        int idx = t + i * 256;
        int k = idx / (NOUT / 4);
        int n = (idx % (NOUT / 4)) * 4;
        float4 v = *(const float4*)&W[k * NOUT + n];
        *(float4*)&Ws[k * WSTR + n] = v;
    }
    __syncthreads();

    float acc[2][NA][4];
#pragma unroll
    for (int ma = 0; ma < 2; ma++)
#pragma unroll
        for (int na = 0; na < NA; na++)
#pragma unroll
            for (int j = 0; j < 4; j++) acc[ma][na][j] = 0.f;

    const int fr = lane >> 2;
    const int fc = lane & 3;
    const int mrow = (wid & 1) * 32;
    const int ncol = (wid >> 1) * WN;

#pragma unroll
    for (int ks = 0; ks < 16; ks++) {
        const int k0 = ks * 8;
        uint32_t ah[2][4], al[2][4];
#pragma unroll
        for (int ma = 0; ma < 2; ma++) {
            int rb = mrow + ma * 16 + fr;
            split_tf32(As[rb * ASTR + k0 + fc],            ah[ma][0], al[ma][0]);
            split_tf32(As[(rb + 8) * ASTR + k0 + fc],      ah[ma][1], al[ma][1]);
            split_tf32(As[rb * ASTR + k0 + fc + 4],        ah[ma][2], al[ma][2]);
            split_tf32(As[(rb + 8) * ASTR + k0 + fc + 4],  ah[ma][3], al[ma][3]);
        }
        uint32_t bh[NA][2], bl[NA][2];
#pragma unroll
        for (int na = 0; na < NA; na++) {
            int cb = ncol + na * 8 + fr;
            split_tf32(Ws[(k0 + fc) * WSTR + cb],       bh[na][0], bl[na][0]);
            split_tf32(Ws[(k0 + fc + 4) * WSTR + cb],   bh[na][1], bl[na][1]);
        }
#pragma unroll
        for (int ma = 0; ma < 2; ma++)
#pragma unroll
            for (int na = 0; na < NA; na++) {
                mma8(acc[ma][na], ah[ma], bh[na]);
                mma8(acc[ma][na], ah[ma], bl[na]);
                mma8(acc[ma][na], al[ma], bh[na]);
            }
    }

    // ---- epilogue: scale by dis[row], store fp16 ----
#pragma unroll
    for (int ma = 0; ma < 2; ma++) {
        int r0 = row0 + mrow + ma * 16 + fr;
        float d0 = (r0 < NN) ? g_dis[r0] : 0.f;
        float d1 = (r0 + 8 < NN) ? g_dis[r0 + 8] : 0.f;
#pragma unroll
        for (int na = 0; na < NA; na++) {
            int cc = ncol + na * 8 + fc * 2;
            if (r0 < NN)
                *(__half2*)&C[r0 * NOUT + cc] =
                    __floats2half2_rn(acc[ma][na][0] * d0, acc[ma][na][1] * d0);
            if (r0 + 8 < NN)
                *(__half2*)&C[(r0 + 8) * NOUT + cc] =
                    __floats2half2_rn(acc[ma][na][2] * d1, acc[ma][na][3] * d1);
        }
    }
    // zero the dummy pad row (index NN) for the gather
    if (blockIdx.x == 0 && t < NOUT) C[NN * NOUT + t] = __float2half(0.f);
}

// ---------------- CSR gather (128ch, fp16 in / fp16 out) ----------------
// agg[d] = dis[d]*(sum h'[s] + h'[d]) + b ; fused BN stats (fp32 pre-round).
template <int SBUF>
__global__ void k_gather128(const __half* __restrict__ h, __half* __restrict__ agg,
                            const float* __restrict__ b) {
    __shared__ float ssum[8][128], ssum2[8][128];
    int t = threadIdx.x;
    int w = t >> 5, lane = t & 31;
    int d = blockIdx.x * 8 + w;
    float4 out = make_float4(0.f, 0.f, 0.f, 0.f);
    bool valid = d < NN;
    if (valid) {
        float disd = g_dis[d];
        int j = g_rowstart[d];
        int end = g_rowstart[d + 1];
        float4 acc = ld_h4(&h[d * 128 + lane * 4]);   // self term
        const int* cs = (const int*)g_csrc4;
        for (; j < end; j += 4) {
            int4 s4 = *(const int4*)&cs[j];
            float4 v0 = ld_h4(&h[s4.x * 128 + lane * 4]);
            float4 v1 = ld_h4(&h[s4.y * 128 + lane * 4]);
            float4 v2 = ld_h4(&h[s4.z * 128 + lane * 4]);
            float4 v3 = ld_h4(&h[s4.w * 128 + lane * 4]);
            acc.x += (v0.x + v1.x) + (v2.x + v3.x);
            acc.y += (v0.y + v1.y) + (v2.y + v3.y);
            acc.z += (v0.z + v1.z) + (v2.z + v3.z);
            acc.w += (v0.w + v1.w) + (v2.w + v3.w);
        }
        float4 bv = *(const float4*)&b[lane * 4];
        out.x = fmaf(acc.x, disd, bv.x);
        out.y = fmaf(acc.y, disd, bv.y);
        out.z = fmaf(acc.z, disd, bv.z);
        out.w = fmaf(acc.w, disd, bv.w);
        st_h4(&agg[d * 128 + lane * 4], out);
    }
    int c = lane * 4;
    ssum[w][c + 0] = out.x;  ssum2[w][c + 0] = out.x * out.x;
    ssum[w][c + 1] = out.y;  ssum2[w][c + 1] = out.y * out.y;
    ssum[w][c + 2] = out.z;  ssum2[w][c + 2] = out.z * out.z;
    ssum[w][c + 3] = out.w;  ssum2[w][c + 3] = out.w * out.w;
    __syncthreads();
    if (t < 128) {
        float s = 0.f, s2 = 0.f;
#pragma unroll
        for (int ww = 0; ww < 8; ww++) { s += ssum[ww][t]; s2 += ssum2[ww][t]; }
        atomicAdd(&g_stats[SBUF * 256 + t], s);
        atomicAdd(&g_stats[SBUF * 256 + 128 + t], s2);
    }
}

// ---------------- final gather (32ch fp16) fused with log_softmax ----------------
__global__ void k_gather32_lsm(const __half* __restrict__ h, float* __restrict__ out,
                               const float* __restrict__ b) {
    int t = threadIdx.x;
    int w = t >> 5, lane = t & 31;
    int d = blockIdx.x * 8 + w;
    if (d >= NN) return;
    float disd = g_dis[d];
    int j = g_rowstart[d];
    int end = g_rowstart[d + 1];
    float acc = __half2float(h[d * 32 + lane]);
    const int* cs = (const int*)g_csrc4;
    for (; j < end; j += 4) {
        int4 s4 = *(const int4*)&cs[j];
        float v0 = __half2float(h[s4.x * 32 + lane]);
        float v1 = __half2float(h[s4.y * 32 + lane]);
        float v2 = __half2float(h[s4.z * 32 + lane]);
        float v3 = __half2float(h[s4.w * 32 + lane]);
        acc += (v0 + v1) + (v2 + v3);
    }
    float logit = fmaf(acc, disd, b[lane]);
    float m = logit;
#pragma unroll
    for (int o = 16; o > 0; o >>= 1) m = fmaxf(m, __shfl_xor_sync(0xffffffffu, m, o));
    float e = __expf(logit - m);
    float s = e;
#pragma unroll
    for (int o = 16; o > 0; o >>= 1) s += __shfl_xor_sync(0xffffffffu, s, o);
    out[d * 32 + lane] = logit - m - logf(s);
}

// ---------------- launch ----------------
extern "C" void kernel_launch(void* const* d_in, const int* in_sizes, int n_in,
                              void* d_out, int out_size) {
    const float* x   = (const float*)d_in[0];
    const void*  ei  = d_in[1];
    const float* W0  = (const float*)d_in[2];
    const float* b0  = (const float*)d_in[3];
    const float* g0  = (const float*)d_in[4];
    const float* be0 = (const float*)d_in[5];
    const float* W1  = (const float*)d_in[6];
    const float* b1  = (const float*)d_in[7];
    const float* g1  = (const float*)d_in[8];
    const float* be1 = (const float*)d_in[9];
    const float* W2  = (const float*)d_in[10];
    const float* b2  = (const float*)d_in[11];
    float* out = (float*)d_out;

    __half *p_h16, *p_agg16, *p_x16;
    cudaGetSymbolAddress((void**)&p_h16, g_h16);
    cudaGetSymbolAddress((void**)&p_agg16, g_agg16);
    cudaGetSymbolAddress((void**)&p_x16, g_x16);

    // lazily-created side stream + fork/join events (created on first,
    // uncaptured call; identical GPU work every call)
    static cudaStream_t s2 = nullptr;
    static cudaEvent_t evA = nullptr, evB = nullptr;
    if (!s2) {
        cudaStreamCreateWithFlags(&s2, cudaStreamNonBlocking);
        cudaEventCreateWithFlags(&evA, cudaEventDisableTiming);
        cudaEventCreateWithFlags(&evB, cudaEventDisableTiming);
    }

    const int initBlocks = (CSRC_CAP / 4 + 255) / 256;
    const int nodeBlocks = (NN + 255) / 256;
    const int edgeBlocks = (NE + 255) / 256;
    const int gatherBlocks = (NN + 7) / 8;
    const int mgemmBlocks = (NN + 63) / 64;

    const int SM128 = (64 * 132 + 128 * 136) * 4; // 103424
    const int SM32  = (64 * 132 + 128 * 40) * 4;  // 54272
    cudaFuncSetAttribute(k_mgemm<128, 0, 0, 0, 0>, cudaFuncAttributeMaxDynamicSharedMemorySize, SM128);
    cudaFuncSetAttribute(k_mgemm<128, 1, 0, 1, 0>, cudaFuncAttributeMaxDynamicSharedMemorySize, SM128);
    cudaFuncSetAttribute(k_mgemm<32, 2, 1, 1, 1>,  cudaFuncAttributeMaxDynamicSharedMemorySize, SM32);

    // ---- preprocessing trunk ----
    k_init0<<<initBlocks, 256>>>((const int*)ei);
    k_deg<<<edgeBlocks, 256>>>(ei);
    cudaEventRecord(evA, 0);

    // side stream: CSR build (needs only deg)
    cudaStreamWaitEvent(s2, evA, 0);
    k_scan1<<<NB1, 1024, 0, s2>>>();
    k_scan3<<<nodeBlocks, 256, 0, s2>>>();
    k_fill<<<edgeBlocks, 256, 0, s2>>>(ei);
    cudaEventRecord(evB, s2);

    // main stream: dis + GEMM0 overlap the CSR build
    k_dis<<<nodeBlocks, 256>>>();
    k_mgemm<128, 0, 0, 0, 0><<<mgemmBlocks, 256, SM128>>>(
        x, W0, p_h16, nullptr, nullptr, nullptr, nullptr);
    cudaStreamWaitEvent(0, evB, 0);

    // ---- layer 0 gather ----
    k_gather128<0><<<gatherBlocks, 256>>>(p_h16, p_agg16, b0);

    // ---- layer 1 ----
    k_mgemm<128, 1, 0, 1, 0><<<mgemmBlocks, 256, SM128>>>(
        p_agg16, W1, p_h16, x, p_x16, g0, be0);
    k_gather128<1><<<gatherBlocks, 256>>>(p_h16, p_agg16, b1);

    // ---- final conv + fused log_softmax ----
    k_mgemm<32, 2, 1, 1, 1><<<mgemmBlocks, 256, SM32>>>(
        p_agg16, W2, p_h16, p_x16, nullptr, g1, be1);
    k_gather32_lsm<<<gatherBlocks, 256>>>(p_h16, out, b2);
}